// round 1
// baseline (speedup 1.0000x reference)
#include <cuda_runtime.h>
#include <cuda_bf16.h>
#include <math.h>
#include <float.h>

// ---------------------------------------------------------------------------
// Problem constants: B=4, N=2048, C=768, H=12, D=64, MLP=3072
// ---------------------------------------------------------------------------
#define MROWS 8192          // B*N
#define CDIM  768
#define C3    2304
#define HID   3072
#define NHEAD 12
#define HDIM  64
#define SEQ   2048
#define LN_EPS 1e-6f

// ---------------------------------------------------------------------------
// Scratch (device globals; no allocation allowed)
// ---------------------------------------------------------------------------
__device__ float g_ln  [MROWS * CDIM];   // LN1 out, later reused for LN2 out
__device__ float g_qkv [MROWS * C3];
__device__ float g_attn[MROWS * CDIM];
__device__ float g_x1  [MROWS * CDIM];
__device__ float g_act [MROWS * HID];

// ---------------------------------------------------------------------------
// LayerNorm: one block (256 threads) per row of 768
// ---------------------------------------------------------------------------
__device__ __forceinline__ float block_reduce_sum(float v, float* sbuf) {
    #pragma unroll
    for (int o = 16; o > 0; o >>= 1) v += __shfl_down_sync(0xffffffffu, v, o);
    int w = threadIdx.x >> 5;
    if ((threadIdx.x & 31) == 0) sbuf[w] = v;
    __syncthreads();
    if (threadIdx.x < 8) {
        v = sbuf[threadIdx.x];
        #pragma unroll
        for (int o = 4; o > 0; o >>= 1) v += __shfl_down_sync(0xffu, v, o);
        if (threadIdx.x == 0) sbuf[0] = v;
    }
    __syncthreads();
    float r = sbuf[0];
    __syncthreads();
    return r;
}

__global__ void layernorm_kernel(const float* __restrict__ x,
                                 const float* __restrict__ g,
                                 const float* __restrict__ b,
                                 float* __restrict__ out) {
    __shared__ float sbuf[8];
    int row = blockIdx.x;
    const float* xr = x + (size_t)row * CDIM;
    float v[3];
    float s = 0.f;
    #pragma unroll
    for (int i = 0; i < 3; i++) {
        v[i] = xr[threadIdx.x + i * 256];
        s += v[i];
    }
    float mu = block_reduce_sum(s, sbuf) * (1.0f / CDIM);
    float s2 = 0.f;
    #pragma unroll
    for (int i = 0; i < 3; i++) {
        float d = v[i] - mu;
        s2 += d * d;
    }
    float var = block_reduce_sum(s2, sbuf) * (1.0f / CDIM);
    float rs = rsqrtf(var + LN_EPS);
    float* orow = out + (size_t)row * CDIM;
    #pragma unroll
    for (int i = 0; i < 3; i++) {
        int c = threadIdx.x + i * 256;
        orow[c] = (v[i] - mu) * rs * g[c] + b[c];
    }
}

// ---------------------------------------------------------------------------
// SGEMM: C[M,N] = A[M,K] @ B[K,N] + bias (+gelu) (+residual)
// BM=BN=128, BK=16, 256 threads, 8x8 microtile. All dims divide tiles exactly.
// ---------------------------------------------------------------------------
#define BM 128
#define BN 128
#define BK 16
#define TM 8
#define TN 8

template<bool GELU, bool RES>
__global__ __launch_bounds__(256, 2)
void sgemm_kernel(int M, int N, int K,
                  const float* __restrict__ A,
                  const float* __restrict__ B,
                  const float* __restrict__ bias,
                  const float* __restrict__ res,
                  float* __restrict__ C) {
    __shared__ float As[BK][BM];
    __shared__ float Bs[BK][BN];

    const int tid  = threadIdx.x;
    const int brow = blockIdx.y;
    const int bcol = blockIdx.x;

    const float* Ag = A + (size_t)brow * BM * K;
    const float* Bg = B + (size_t)bcol * BN;

    const int arow  = tid >> 2;      // 0..63 (rows arow, arow+64)
    const int acol4 = tid & 3;       // float4 col within BK
    const int brl   = tid >> 5;      // 0..7 (rows brl, brl+8)
    const int bc4   = tid & 31;      // float4 col within BN

    const int threadRow = tid >> 4;  // 0..15
    const int threadCol = tid & 15;  // 0..15

    float acc[TM][TN] = {};

    for (int k0 = 0; k0 < K; k0 += BK) {
        #pragma unroll
        for (int i = 0; i < 2; i++) {
            int r = arow + i * 64;
            float4 v = *(const float4*)(Ag + (size_t)r * K + k0 + acol4 * 4);
            As[acol4 * 4 + 0][r] = v.x;
            As[acol4 * 4 + 1][r] = v.y;
            As[acol4 * 4 + 2][r] = v.z;
            As[acol4 * 4 + 3][r] = v.w;
        }
        #pragma unroll
        for (int i = 0; i < 2; i++) {
            int r = brl + i * 8;
            float4 v = *(const float4*)(Bg + (size_t)(k0 + r) * N + bc4 * 4);
            *(float4*)(&Bs[r][bc4 * 4]) = v;
        }
        __syncthreads();

        #pragma unroll
        for (int kk = 0; kk < BK; kk++) {
            float ra[TM], rb[TN];
            #pragma unroll
            for (int i = 0; i < TM; i++) ra[i] = As[kk][threadRow * TM + i];
            #pragma unroll
            for (int j = 0; j < TN; j++) rb[j] = Bs[kk][threadCol * TN + j];
            #pragma unroll
            for (int i = 0; i < TM; i++)
                #pragma unroll
                for (int j = 0; j < TN; j++)
                    acc[i][j] = fmaf(ra[i], rb[j], acc[i][j]);
        }
        __syncthreads();
    }

    const int row0 = brow * BM + threadRow * TM;
    const int col0 = bcol * BN + threadCol * TN;
    #pragma unroll
    for (int i = 0; i < TM; i++) {
        #pragma unroll
        for (int j = 0; j < TN; j++) {
            float v = acc[i][j] + bias[col0 + j];
            if (GELU) v = 0.5f * v * (1.0f + erff(v * 0.70710678118654752f));
            if (RES)  v += res[(size_t)(row0 + i) * N + col0 + j];
            C[(size_t)(row0 + i) * N + col0 + j] = v;
        }
    }
}

// ---------------------------------------------------------------------------
// Fused attention (flash-style): grid (N/64, B*H), 256 threads.
// BQ=64 queries per block, BKV=32 keys per inner tile, D=64. fp32 throughout.
// Q/K/V read strided from the fused qkv buffer; output written in (b,t,h*64+d).
// ---------------------------------------------------------------------------
__global__ __launch_bounds__(256, 2)
void attn_kernel(const float* __restrict__ qkv,
                 const int* __restrict__ mask,
                 float* __restrict__ out) {
    __shared__ float Qs[64][68];
    __shared__ float Ks[32][68];
    __shared__ float Vs[32][68];
    __shared__ float Ss[64][36];
    __shared__ float m_s[64], l_s[64], corr_s[64];
    __shared__ int   msk[32];

    const int tid = threadIdx.x;
    const int bh  = blockIdx.y;
    const int bb  = bh / NHEAD;
    const int hh  = bh % NHEAD;
    const int q0  = blockIdx.x * 64;

    const size_t base = (size_t)bb * SEQ * C3;
    const int qoff = hh * HDIM;

    // load Q tile
    for (int idx = tid; idx < 64 * 64; idx += 256) {
        int r = idx >> 6, c = idx & 63;
        Qs[r][c] = qkv[base + (size_t)(q0 + r) * C3 + qoff + c];
    }
    if (tid < 64) { m_s[tid] = -FLT_MAX; l_s[tid] = 0.f; }

    const int ty = tid >> 4;   // 0..15
    const int tx = tid & 15;   // 0..15
    float o[4][4] = {};

    for (int kt = 0; kt < SEQ; kt += 32) {
        __syncthreads();   // protects Qs (first iter) + Ks/Vs/Ss reuse
        for (int idx = tid; idx < 32 * 64; idx += 256) {
            int r = idx >> 6, c = idx & 63;
            size_t rowb = base + (size_t)(kt + r) * C3 + qoff;
            Ks[r][c] = qkv[rowb + CDIM + c];
            Vs[r][c] = qkv[rowb + 2 * CDIM + c];
        }
        if (tid < 32) msk[tid] = mask[bb * SEQ + kt + tid];
        __syncthreads();

        // S tile: rows ty*4+i, cols tx*2+j
        float sacc[4][2] = {};
        #pragma unroll 16
        for (int kk = 0; kk < 64; kk++) {
            float qv[4], kv[2];
            #pragma unroll
            for (int i = 0; i < 4; i++) qv[i] = Qs[ty * 4 + i][kk];
            #pragma unroll
            for (int j = 0; j < 2; j++) kv[j] = Ks[tx * 2 + j][kk];
            #pragma unroll
            for (int i = 0; i < 4; i++)
                #pragma unroll
                for (int j = 0; j < 2; j++)
                    sacc[i][j] = fmaf(qv[i], kv[j], sacc[i][j]);
        }
        #pragma unroll
        for (int i = 0; i < 4; i++)
            #pragma unroll
            for (int j = 0; j < 2; j++) {
                float sv = sacc[i][j] * 0.125f;
                if (msk[tx * 2 + j] == 0) sv = -FLT_MAX;
                Ss[ty * 4 + i][tx * 2 + j] = sv;
            }
        __syncthreads();

        // online softmax per row (64 rows handled by first 64 threads)
        if (tid < 64) {
            float mo = m_s[tid];
            float mx = mo;
            #pragma unroll 8
            for (int c = 0; c < 32; c++) mx = fmaxf(mx, Ss[tid][c]);
            float corr = expf(mo - mx);
            float lsum = 0.f;
            #pragma unroll 8
            for (int c = 0; c < 32; c++) {
                float p = expf(Ss[tid][c] - mx);
                Ss[tid][c] = p;
                lsum += p;
            }
            m_s[tid] = mx;
            l_s[tid] = l_s[tid] * corr + lsum;
            corr_s[tid] = corr;
        }
        __syncthreads();

        // O = O*corr + P @ V ; thread owns O[ty*4+i][tx*4+j]
        float cr[4];
        #pragma unroll
        for (int i = 0; i < 4; i++) cr[i] = corr_s[ty * 4 + i];
        #pragma unroll
        for (int i = 0; i < 4; i++)
            #pragma unroll
            for (int j = 0; j < 4; j++) o[i][j] *= cr[i];
        #pragma unroll 8
        for (int kk = 0; kk < 32; kk++) {
            float pv[4], vv[4];
            #pragma unroll
            for (int i = 0; i < 4; i++) pv[i] = Ss[ty * 4 + i][kk];
            #pragma unroll
            for (int j = 0; j < 4; j++) vv[j] = Vs[kk][tx * 4 + j];
            #pragma unroll
            for (int i = 0; i < 4; i++)
                #pragma unroll
                for (int j = 0; j < 4; j++)
                    o[i][j] = fmaf(pv[i], vv[j], o[i][j]);
        }
    }
    __syncthreads();

    float li[4];
    #pragma unroll
    for (int i = 0; i < 4; i++) li[i] = 1.0f / l_s[ty * 4 + i];
    #pragma unroll
    for (int i = 0; i < 4; i++) {
        size_t row = (size_t)(bb * SEQ + q0 + ty * 4 + i);
        #pragma unroll
        for (int j = 0; j < 4; j++)
            out[row * CDIM + qoff + tx * 4 + j] = o[i][j] * li[i];
    }
}

// ---------------------------------------------------------------------------
// Launch
// ---------------------------------------------------------------------------
extern "C" void kernel_launch(void* const* d_in, const int* in_sizes, int n_in,
                              void* d_out, int out_size) {
    const float* x      = (const float*)d_in[0];
    const int*   mask   = (const int*)  d_in[1];
    const float* ln1_g  = (const float*)d_in[2];
    const float* ln1_b  = (const float*)d_in[3];
    const float* qkv_w  = (const float*)d_in[4];
    const float* qkv_b  = (const float*)d_in[5];
    const float* proj_w = (const float*)d_in[6];
    const float* proj_b = (const float*)d_in[7];
    const float* ln2_g  = (const float*)d_in[8];
    const float* ln2_b  = (const float*)d_in[9];
    const float* fc1_w  = (const float*)d_in[10];
    const float* fc1_b  = (const float*)d_in[11];
    const float* fc2_w  = (const float*)d_in[12];
    const float* fc2_b  = (const float*)d_in[13];
    float* out = (float*)d_out;

    float *p_ln, *p_qkv, *p_attn, *p_x1, *p_act;
    cudaGetSymbolAddress((void**)&p_ln,   g_ln);
    cudaGetSymbolAddress((void**)&p_qkv,  g_qkv);
    cudaGetSymbolAddress((void**)&p_attn, g_attn);
    cudaGetSymbolAddress((void**)&p_x1,   g_x1);
    cudaGetSymbolAddress((void**)&p_act,  g_act);

    // 1) LN1
    layernorm_kernel<<<MROWS, 256>>>(x, ln1_g, ln1_b, p_ln);

    // 2) QKV GEMM: [8192,768] @ [768,2304]
    sgemm_kernel<false, false><<<dim3(C3 / BN, MROWS / BM), 256>>>(
        MROWS, C3, CDIM, p_ln, qkv_w, qkv_b, nullptr, p_qkv);

    // 3) fused attention
    attn_kernel<<<dim3(SEQ / 64, 4 * NHEAD), 256>>>(p_qkv, mask, p_attn);

    // 4) proj GEMM + residual: x1 = x + attn @ proj_w + proj_b
    sgemm_kernel<false, true><<<dim3(CDIM / BN, MROWS / BM), 256>>>(
        MROWS, CDIM, CDIM, p_attn, proj_w, proj_b, x, p_x1);

    // 5) LN2
    layernorm_kernel<<<MROWS, 256>>>(p_x1, ln2_g, ln2_b, p_ln);

    // 6) FC1 + exact GELU: [8192,768] @ [768,3072]
    sgemm_kernel<true, false><<<dim3(HID / BN, MROWS / BM), 256>>>(
        MROWS, HID, CDIM, p_ln, fc1_w, fc1_b, nullptr, p_act);

    // 7) FC2 + residual -> out: [8192,3072] @ [3072,768]
    sgemm_kernel<false, true><<<dim3(CDIM / BN, MROWS / BM), 256>>>(
        MROWS, CDIM, HID, p_act, fc2_w, fc2_b, p_x1, out);
}

// round 2
// speedup vs baseline: 1.4815x; 1.4815x over previous
#include <cuda_runtime.h>
#include <cuda_bf16.h>
#include <math.h>
#include <float.h>

// ---------------------------------------------------------------------------
// Problem constants: B=4, N=2048, C=768, H=12, D=64, MLP=3072
// ---------------------------------------------------------------------------
#define MROWS 8192          // B*N
#define CDIM  768
#define C3    2304
#define HID   3072
#define NHEAD 12
#define HDIM  64
#define SEQ   2048
#define LN_EPS 1e-6f

// ---------------------------------------------------------------------------
// Scratch (device globals; no allocation allowed)
// ---------------------------------------------------------------------------
__device__ float g_ln  [MROWS * CDIM];
__device__ float g_qkv [MROWS * C3];
__device__ float g_attn[MROWS * CDIM];
__device__ float g_x1  [MROWS * CDIM];
__device__ float g_act [MROWS * HID];

// ---------------------------------------------------------------------------
// helpers
// ---------------------------------------------------------------------------
__device__ __forceinline__ unsigned f2tf32(float x) {
    unsigned r;
    asm("cvt.rna.tf32.f32 %0, %1;" : "=r"(r) : "f"(x));
    return r;
}

#define MMA_TF32(d, a, b)                                                     \
    asm volatile(                                                             \
        "mma.sync.aligned.m16n8k8.row.col.f32.tf32.tf32.f32 "                 \
        "{%0,%1,%2,%3}, {%4,%5,%6,%7}, {%8,%9}, {%0,%1,%2,%3};\n"             \
        : "+f"(d[0]), "+f"(d[1]), "+f"(d[2]), "+f"(d[3])                      \
        : "r"(a[0]), "r"(a[1]), "r"(a[2]), "r"(a[3]), "r"(b[0]), "r"(b[1]))

// ---------------------------------------------------------------------------
// LayerNorm: one block (256 threads) per row of 768
// ---------------------------------------------------------------------------
__device__ __forceinline__ float block_reduce_sum(float v, float* sbuf) {
    #pragma unroll
    for (int o = 16; o > 0; o >>= 1) v += __shfl_down_sync(0xffffffffu, v, o);
    int w = threadIdx.x >> 5;
    if ((threadIdx.x & 31) == 0) sbuf[w] = v;
    __syncthreads();
    if (threadIdx.x < 8) {
        v = sbuf[threadIdx.x];
        #pragma unroll
        for (int o = 4; o > 0; o >>= 1) v += __shfl_down_sync(0xffu, v, o);
        if (threadIdx.x == 0) sbuf[0] = v;
    }
    __syncthreads();
    float r = sbuf[0];
    __syncthreads();
    return r;
}

__global__ void layernorm_kernel(const float* __restrict__ x,
                                 const float* __restrict__ g,
                                 const float* __restrict__ b,
                                 float* __restrict__ out) {
    __shared__ float sbuf[8];
    int row = blockIdx.x;
    const float* xr = x + (size_t)row * CDIM;
    float v[3];
    float s = 0.f;
    #pragma unroll
    for (int i = 0; i < 3; i++) {
        v[i] = xr[threadIdx.x + i * 256];
        s += v[i];
    }
    float mu = block_reduce_sum(s, sbuf) * (1.0f / CDIM);
    float s2 = 0.f;
    #pragma unroll
    for (int i = 0; i < 3; i++) {
        float d = v[i] - mu;
        s2 += d * d;
    }
    float var = block_reduce_sum(s2, sbuf) * (1.0f / CDIM);
    float rs = rsqrtf(var + LN_EPS);
    float* orow = out + (size_t)row * CDIM;
    #pragma unroll
    for (int i = 0; i < 3; i++) {
        int c = threadIdx.x + i * 256;
        orow[c] = (v[i] - mu) * rs * g[c] + b[c];
    }
}

// ---------------------------------------------------------------------------
// TF32 tensor-core GEMM: C[M,N] = A[M,K] @ B[K,N] + bias (+gelu) (+residual)
// BM=BN=128, BK=16, 256 threads (8 warps, 2x4), warp tile 64x32 via m16n8k8.
// SMEM stride 136 floats -> conflict-free fragment loads.
// ---------------------------------------------------------------------------
#define BM 128
#define BN 128
#define BK 16
#define LDS_STRIDE 136

template<bool GELU, bool RES>
__global__ __launch_bounds__(256, 2)
void gemm_tc(int M, int N, int K,
             const float* __restrict__ A,
             const float* __restrict__ B,
             const float* __restrict__ bias,
             const float* __restrict__ res,
             float* __restrict__ C) {
    __shared__ float As[BK][LDS_STRIDE];   // [k][m]
    __shared__ float Bs[BK][LDS_STRIDE];   // [k][n]

    const int tid  = threadIdx.x;
    const int lane = tid & 31;
    const int wid  = tid >> 5;
    const int wm   = (wid >> 2) * 64;      // warp m-offset (0 / 64)
    const int wn   = (wid & 3) * 32;       // warp n-offset (0/32/64/96)

    const float* Ag = A + (size_t)blockIdx.y * BM * K;
    const float* Bg = B + (size_t)blockIdx.x * BN;

    // global->smem mapping
    const int arow = tid >> 2;             // 0..63 (rows arow, arow+64)
    const int ac   = (tid & 3) * 4;        // k-col base
    const int brl  = tid >> 5;             // 0..7  (rows brl, brl+8)
    const int bc   = (tid & 31) * 4;       // n-col base

    float acc[4][4][4] = {};               // [mi][ni][reg]

    const int gr = lane >> 2;              // group row 0..7
    const int kq = lane & 3;               // thread-in-group 0..3

    for (int k0 = 0; k0 < K; k0 += BK) {
        #pragma unroll
        for (int i = 0; i < 2; i++) {
            int r = arow + i * 64;
            float4 v = *(const float4*)(Ag + (size_t)r * K + k0 + ac);
            As[ac + 0][r] = __uint_as_float(f2tf32(v.x));
            As[ac + 1][r] = __uint_as_float(f2tf32(v.y));
            As[ac + 2][r] = __uint_as_float(f2tf32(v.z));
            As[ac + 3][r] = __uint_as_float(f2tf32(v.w));
        }
        #pragma unroll
        for (int i = 0; i < 2; i++) {
            int r = brl + i * 8;
            float4 v = *(const float4*)(Bg + (size_t)(k0 + r) * N + bc);
            float4 t;
            t.x = __uint_as_float(f2tf32(v.x));
            t.y = __uint_as_float(f2tf32(v.y));
            t.z = __uint_as_float(f2tf32(v.z));
            t.w = __uint_as_float(f2tf32(v.w));
            *(float4*)(&Bs[r][bc]) = t;
        }
        __syncthreads();

        #pragma unroll
        for (int ks = 0; ks < BK; ks += 8) {
            unsigned a[4][4], b[4][2];
            #pragma unroll
            for (int mi = 0; mi < 4; mi++) {
                int m = wm + mi * 16 + gr;
                a[mi][0] = __float_as_uint(As[ks + kq    ][m]);
                a[mi][1] = __float_as_uint(As[ks + kq    ][m + 8]);
                a[mi][2] = __float_as_uint(As[ks + kq + 4][m]);
                a[mi][3] = __float_as_uint(As[ks + kq + 4][m + 8]);
            }
            #pragma unroll
            for (int ni = 0; ni < 4; ni++) {
                int n = wn + ni * 8 + gr;
                b[ni][0] = __float_as_uint(Bs[ks + kq    ][n]);
                b[ni][1] = __float_as_uint(Bs[ks + kq + 4][n]);
            }
            #pragma unroll
            for (int mi = 0; mi < 4; mi++)
                #pragma unroll
                for (int ni = 0; ni < 4; ni++)
                    MMA_TF32(acc[mi][ni], a[mi], b[ni]);
        }
        __syncthreads();
    }

    // epilogue
    #pragma unroll
    for (int mi = 0; mi < 4; mi++) {
        #pragma unroll
        for (int ni = 0; ni < 4; ni++) {
            int row = blockIdx.y * BM + wm + mi * 16 + gr;
            int col = blockIdx.x * BN + wn + ni * 8 + kq * 2;
            #pragma unroll
            for (int h = 0; h < 2; h++) {      // h=0 -> rows row; h=1 -> row+8
                int r = row + h * 8;
                float v0 = acc[mi][ni][h * 2 + 0] + bias[col];
                float v1 = acc[mi][ni][h * 2 + 1] + bias[col + 1];
                if (GELU) {
                    v0 = 0.5f * v0 * (1.0f + erff(v0 * 0.70710678118654752f));
                    v1 = 0.5f * v1 * (1.0f + erff(v1 * 0.70710678118654752f));
                }
                if (RES) {
                    v0 += res[(size_t)r * N + col];
                    v1 += res[(size_t)r * N + col + 1];
                }
                C[(size_t)r * N + col]     = v0;
                C[(size_t)r * N + col + 1] = v1;
            }
        }
    }
}

// ---------------------------------------------------------------------------
// Fused attention (flash-style): grid (N/64, B*H), 256 threads. fp32 SIMT.
// ---------------------------------------------------------------------------
__global__ __launch_bounds__(256, 2)
void attn_kernel(const float* __restrict__ qkv,
                 const int* __restrict__ mask,
                 float* __restrict__ out) {
    __shared__ float Qs[64][68];
    __shared__ float Ks[32][68];
    __shared__ float Vs[32][68];
    __shared__ float Ss[64][36];
    __shared__ float m_s[64], l_s[64], corr_s[64];
    __shared__ int   msk[32];

    const int tid = threadIdx.x;
    const int bh  = blockIdx.y;
    const int bb  = bh / NHEAD;
    const int hh  = bh % NHEAD;
    const int q0  = blockIdx.x * 64;

    const size_t base = (size_t)bb * SEQ * C3;
    const int qoff = hh * HDIM;

    for (int idx = tid; idx < 64 * 64; idx += 256) {
        int r = idx >> 6, c = idx & 63;
        Qs[r][c] = qkv[base + (size_t)(q0 + r) * C3 + qoff + c];
    }
    if (tid < 64) { m_s[tid] = -FLT_MAX; l_s[tid] = 0.f; }

    const int ty = tid >> 4;
    const int tx = tid & 15;
    float o[4][4] = {};

    for (int kt = 0; kt < SEQ; kt += 32) {
        __syncthreads();
        for (int idx = tid; idx < 32 * 64; idx += 256) {
            int r = idx >> 6, c = idx & 63;
            size_t rowb = base + (size_t)(kt + r) * C3 + qoff;
            Ks[r][c] = qkv[rowb + CDIM + c];
            Vs[r][c] = qkv[rowb + 2 * CDIM + c];
        }
        if (tid < 32) msk[tid] = mask[bb * SEQ + kt + tid];
        __syncthreads();

        float sacc[4][2] = {};
        #pragma unroll 16
        for (int kk = 0; kk < 64; kk++) {
            float qv[4], kv[2];
            #pragma unroll
            for (int i = 0; i < 4; i++) qv[i] = Qs[ty * 4 + i][kk];
            #pragma unroll
            for (int j = 0; j < 2; j++) kv[j] = Ks[tx * 2 + j][kk];
            #pragma unroll
            for (int i = 0; i < 4; i++)
                #pragma unroll
                for (int j = 0; j < 2; j++)
                    sacc[i][j] = fmaf(qv[i], kv[j], sacc[i][j]);
        }
        #pragma unroll
        for (int i = 0; i < 4; i++)
            #pragma unroll
            for (int j = 0; j < 2; j++) {
                float sv = sacc[i][j] * 0.125f;
                if (msk[tx * 2 + j] == 0) sv = -FLT_MAX;
                Ss[ty * 4 + i][tx * 2 + j] = sv;
            }
        __syncthreads();

        if (tid < 64) {
            float mo = m_s[tid];
            float mx = mo;
            #pragma unroll 8
            for (int c = 0; c < 32; c++) mx = fmaxf(mx, Ss[tid][c]);
            float corr = expf(mo - mx);
            float lsum = 0.f;
            #pragma unroll 8
            for (int c = 0; c < 32; c++) {
                float p = expf(Ss[tid][c] - mx);
                Ss[tid][c] = p;
                lsum += p;
            }
            m_s[tid] = mx;
            l_s[tid] = l_s[tid] * corr + lsum;
            corr_s[tid] = corr;
        }
        __syncthreads();

        float cr[4];
        #pragma unroll
        for (int i = 0; i < 4; i++) cr[i] = corr_s[ty * 4 + i];
        #pragma unroll
        for (int i = 0; i < 4; i++)
            #pragma unroll
            for (int j = 0; j < 4; j++) o[i][j] *= cr[i];
        #pragma unroll 8
        for (int kk = 0; kk < 32; kk++) {
            float pv[4], vv[4];
            #pragma unroll
            for (int i = 0; i < 4; i++) pv[i] = Ss[ty * 4 + i][kk];
            #pragma unroll
            for (int j = 0; j < 4; j++) vv[j] = Vs[kk][tx * 4 + j];
            #pragma unroll
            for (int i = 0; i < 4; i++)
                #pragma unroll
                for (int j = 0; j < 4; j++)
                    o[i][j] = fmaf(pv[i], vv[j], o[i][j]);
        }
    }
    __syncthreads();

    float li[4];
    #pragma unroll
    for (int i = 0; i < 4; i++) li[i] = 1.0f / l_s[ty * 4 + i];
    #pragma unroll
    for (int i = 0; i < 4; i++) {
        size_t row = (size_t)(bb * SEQ + q0 + ty * 4 + i);
        #pragma unroll
        for (int j = 0; j < 4; j++)
            out[row * CDIM + qoff + tx * 4 + j] = o[i][j] * li[i];
    }
}

// ---------------------------------------------------------------------------
// Launch
// ---------------------------------------------------------------------------
extern "C" void kernel_launch(void* const* d_in, const int* in_sizes, int n_in,
                              void* d_out, int out_size) {
    const float* x      = (const float*)d_in[0];
    const int*   mask   = (const int*)  d_in[1];
    const float* ln1_g  = (const float*)d_in[2];
    const float* ln1_b  = (const float*)d_in[3];
    const float* qkv_w  = (const float*)d_in[4];
    const float* qkv_b  = (const float*)d_in[5];
    const float* proj_w = (const float*)d_in[6];
    const float* proj_b = (const float*)d_in[7];
    const float* ln2_g  = (const float*)d_in[8];
    const float* ln2_b  = (const float*)d_in[9];
    const float* fc1_w  = (const float*)d_in[10];
    const float* fc1_b  = (const float*)d_in[11];
    const float* fc2_w  = (const float*)d_in[12];
    const float* fc2_b  = (const float*)d_in[13];
    float* out = (float*)d_out;

    float *p_ln, *p_qkv, *p_attn, *p_x1, *p_act;
    cudaGetSymbolAddress((void**)&p_ln,   g_ln);
    cudaGetSymbolAddress((void**)&p_qkv,  g_qkv);
    cudaGetSymbolAddress((void**)&p_attn, g_attn);
    cudaGetSymbolAddress((void**)&p_x1,   g_x1);
    cudaGetSymbolAddress((void**)&p_act,  g_act);

    // 1) LN1
    layernorm_kernel<<<MROWS, 256>>>(x, ln1_g, ln1_b, p_ln);

    // 2) QKV GEMM: [8192,768] @ [768,2304]
    gemm_tc<false, false><<<dim3(C3 / BN, MROWS / BM), 256>>>(
        MROWS, C3, CDIM, p_ln, qkv_w, qkv_b, nullptr, p_qkv);

    // 3) fused attention
    attn_kernel<<<dim3(SEQ / 64, 4 * NHEAD), 256>>>(p_qkv, mask, p_attn);

    // 4) proj GEMM + residual
    gemm_tc<false, true><<<dim3(CDIM / BN, MROWS / BM), 256>>>(
        MROWS, CDIM, CDIM, p_attn, proj_w, proj_b, x, p_x1);

    // 5) LN2
    layernorm_kernel<<<MROWS, 256>>>(p_x1, ln2_g, ln2_b, p_ln);

    // 6) FC1 + exact GELU
    gemm_tc<true, false><<<dim3(HID / BN, MROWS / BM), 256>>>(
        MROWS, HID, CDIM, p_ln, fc1_w, fc1_b, nullptr, p_act);

    // 7) FC2 + residual -> out
    gemm_tc<false, true><<<dim3(CDIM / BN, MROWS / BM), 256>>>(
        MROWS, CDIM, HID, p_act, fc2_w, fc2_b, p_x1, out);
}

// round 5
// speedup vs baseline: 3.6401x; 2.4570x over previous
#include <cuda_runtime.h>
#include <cuda_bf16.h>
#include <math.h>
#include <float.h>

// ---------------------------------------------------------------------------
// Problem constants: B=4, N=2048, C=768, H=12, D=64, MLP=3072
// ---------------------------------------------------------------------------
#define MROWS 8192          // B*N
#define CDIM  768
#define C3    2304
#define HID   3072
#define NHEAD 12
#define HDIM  64
#define SEQ   2048
#define LN_EPS 1e-6f

// ---------------------------------------------------------------------------
// Scratch (device globals; no allocation allowed)
// ---------------------------------------------------------------------------
__device__ float g_ln  [MROWS * CDIM];
__device__ float g_qkv [MROWS * C3];
__device__ float g_attn[MROWS * CDIM];
__device__ float g_x1  [MROWS * CDIM];
__device__ float g_act [MROWS * HID];

// ---------------------------------------------------------------------------
// helpers
// ---------------------------------------------------------------------------
#define MMA_TF32(d, a, b)                                                     \
    asm volatile(                                                             \
        "mma.sync.aligned.m16n8k8.row.col.f32.tf32.tf32.f32 "                 \
        "{%0,%1,%2,%3}, {%4,%5,%6,%7}, {%8,%9}, {%0,%1,%2,%3};\n"             \
        : "+f"(d[0]), "+f"(d[1]), "+f"(d[2]), "+f"(d[3])                      \
        : "r"(a[0]), "r"(a[1]), "r"(a[2]), "r"(a[3]), "r"(b[0]), "r"(b[1]))

__device__ __forceinline__ void cp16(void* dst, const void* src) {
    unsigned s = (unsigned)__cvta_generic_to_shared(dst);
    asm volatile("cp.async.cg.shared.global [%0], [%1], 16;\n" :: "r"(s), "l"(src));
}

// ---------------------------------------------------------------------------
// LayerNorm: warp per row, float4 everywhere. grid = MROWS/8, block 256.
// ---------------------------------------------------------------------------
__global__ void layernorm_kernel(const float* __restrict__ x,
                                 const float* __restrict__ g,
                                 const float* __restrict__ b,
                                 float* __restrict__ out) {
    const int row  = blockIdx.x * 8 + (threadIdx.x >> 5);
    const int lane = threadIdx.x & 31;
    const float* xr = x + (size_t)row * CDIM;

    float4 v[6];
    float s = 0.f;
    #pragma unroll
    for (int i = 0; i < 6; i++) {
        v[i] = *(const float4*)(xr + lane * 4 + i * 128);
        s += v[i].x + v[i].y + v[i].z + v[i].w;
    }
    #pragma unroll
    for (int o = 16; o > 0; o >>= 1) s += __shfl_xor_sync(0xffffffffu, s, o);
    float mu = s * (1.0f / CDIM);

    float s2 = 0.f;
    #pragma unroll
    for (int i = 0; i < 6; i++) {
        float dx = v[i].x - mu, dy = v[i].y - mu, dz = v[i].z - mu, dw = v[i].w - mu;
        s2 += dx * dx + dy * dy + dz * dz + dw * dw;
    }
    #pragma unroll
    for (int o = 16; o > 0; o >>= 1) s2 += __shfl_xor_sync(0xffffffffu, s2, o);
    float rs = rsqrtf(s2 * (1.0f / CDIM) + LN_EPS);

    float* orow = out + (size_t)row * CDIM;
    #pragma unroll
    for (int i = 0; i < 6; i++) {
        int c = lane * 4 + i * 128;
        float4 gg = *(const float4*)(g + c);
        float4 bb = *(const float4*)(b + c);
        float4 o4;
        o4.x = (v[i].x - mu) * rs * gg.x + bb.x;
        o4.y = (v[i].y - mu) * rs * gg.y + bb.y;
        o4.z = (v[i].z - mu) * rs * gg.z + bb.z;
        o4.w = (v[i].w - mu) * rs * gg.w + bb.w;
        *(float4*)(orow + c) = o4;
    }
}

// ---------------------------------------------------------------------------
// TF32 GEMM, cp.async double-buffered. BM=BN=128, BK=16, 256 threads (8 warps)
// As [buf][128][20] row-major(m,k); Bs [buf][16][136] (k,n). No explicit cvt:
// mma.tf32 ignores low mantissa bits (truncation, ~2^-10 rel — fine vs 1e-3).
// ---------------------------------------------------------------------------
#define BK 16

template<bool GELU, bool RES>
__global__ __launch_bounds__(256, 2)
void gemm_tc(int M, int N, int K,
             const float* __restrict__ A,
             const float* __restrict__ B,
             const float* __restrict__ bias,
             const float* __restrict__ res,
             float* __restrict__ C) {
    __shared__ float As[2][128][20];
    __shared__ float Bs[2][BK][136];

    const int tid  = threadIdx.x;
    const int lane = tid & 31;
    const int wid  = tid >> 5;
    const int gr   = lane >> 2;
    const int kq   = lane & 3;
    const int wm   = (wid >> 2) * 64;
    const int wn   = (wid & 3) * 32;

    const float* Ag = A + (size_t)blockIdx.y * 128 * K;
    const float* Bg = B + (size_t)blockIdx.x * 128;

    float acc[4][4][4] = {};

    auto load_tile = [&](int k0, int buf) {
        #pragma unroll
        for (int i = 0; i < 2; i++) {
            int ch = tid + i * 256;          // 0..511
            int r  = ch >> 2;                // 0..127
            int c4 = (ch & 3) * 4;
            cp16(&As[buf][r][c4], Ag + (size_t)r * K + k0 + c4);
        }
        #pragma unroll
        for (int i = 0; i < 2; i++) {
            int ch = tid + i * 256;
            int r  = ch >> 5;                // 0..15
            int c4 = (ch & 31) * 4;
            cp16(&Bs[buf][r][c4], Bg + (size_t)(k0 + r) * N + c4);
        }
        asm volatile("cp.async.commit_group;\n");
    };

    load_tile(0, 0);
    const int nt = K / BK;
    for (int t = 0; t < nt; t++) {
        const int buf = t & 1;
        if (t + 1 < nt) {
            load_tile((t + 1) * BK, buf ^ 1);
            asm volatile("cp.async.wait_group 1;\n");
        } else {
            asm volatile("cp.async.wait_group 0;\n");
        }
        __syncthreads();

        #pragma unroll
        for (int ks = 0; ks < BK; ks += 8) {
            unsigned a[4][4], b[4][2];
            #pragma unroll
            for (int mi = 0; mi < 4; mi++) {
                int m = wm + mi * 16 + gr;
                a[mi][0] = __float_as_uint(As[buf][m][ks + kq]);
                a[mi][1] = __float_as_uint(As[buf][m + 8][ks + kq]);
                a[mi][2] = __float_as_uint(As[buf][m][ks + kq + 4]);
                a[mi][3] = __float_as_uint(As[buf][m + 8][ks + kq + 4]);
            }
            #pragma unroll
            for (int ni = 0; ni < 4; ni++) {
                int n = wn + ni * 8 + gr;
                b[ni][0] = __float_as_uint(Bs[buf][ks + kq][n]);
                b[ni][1] = __float_as_uint(Bs[buf][ks + kq + 4][n]);
            }
            #pragma unroll
            for (int mi = 0; mi < 4; mi++)
                #pragma unroll
                for (int ni = 0; ni < 4; ni++)
                    MMA_TF32(acc[mi][ni], a[mi], b[ni]);
        }
        __syncthreads();
    }

    #pragma unroll
    for (int mi = 0; mi < 4; mi++) {
        #pragma unroll
        for (int ni = 0; ni < 4; ni++) {
            int row = blockIdx.y * 128 + wm + mi * 16 + gr;
            int col = blockIdx.x * 128 + wn + ni * 8 + kq * 2;
            #pragma unroll
            for (int h = 0; h < 2; h++) {
                int r = row + h * 8;
                float v0 = acc[mi][ni][h * 2 + 0] + bias[col];
                float v1 = acc[mi][ni][h * 2 + 1] + bias[col + 1];
                if (GELU) {
                    v0 = 0.5f * v0 * (1.0f + erff(v0 * 0.70710678118654752f));
                    v1 = 0.5f * v1 * (1.0f + erff(v1 * 0.70710678118654752f));
                }
                if (RES) {
                    v0 += res[(size_t)r * N + col];
                    v1 += res[(size_t)r * N + col + 1];
                }
                C[(size_t)r * N + col]     = v0;
                C[(size_t)r * N + col + 1] = v1;
            }
        }
    }
}

// ---------------------------------------------------------------------------
// Tensor-core flash attention. BQ=128 (warp owns 16 q-rows), BKV=64, D=64.
// TF32 m16n8k8 for S=Q@K^T and O+=P@V. Softmax state in registers
// (quad-shuffle reductions); P via warp-private SMEM. Dynamic smem ~103KB.
// ---------------------------------------------------------------------------
#define ATT_SMEM ((128 * 68 + 64 * 68 + 64 * 72 + 128 * 68) * 4 + 64 * 4)

__global__ __launch_bounds__(256, 1)
void attn_tc(const float* __restrict__ qkv,
             const int* __restrict__ mask,
             float* __restrict__ out) {
    extern __shared__ float sm[];
    float* Qs = sm;                       // [128][68]
    float* Ks = Qs + 128 * 68;            // [64][68]  (natural [t][d])
    float* Vs = Ks + 64 * 68;             // [64][72]  (natural [t][d])
    float* Ps = Vs + 64 * 72;             // [128][68]
    int*   msk = (int*)(Ps + 128 * 68);   // [64]

    const int tid  = threadIdx.x;
    const int lane = tid & 31;
    const int w    = tid >> 5;
    const int gr   = lane >> 2;
    const int kq   = lane & 3;
    const int bb   = blockIdx.y / NHEAD;
    const int hh   = blockIdx.y % NHEAD;
    const int q0   = blockIdx.x * 128;
    const size_t base = (size_t)bb * SEQ * C3;
    const int qoff = hh * HDIM;
    const int qrow = w * 16;

    // Q tile (pre-scaled by 1/sqrt(D))
    #pragma unroll
    for (int i = 0; i < 8; i++) {
        int idx = tid + i * 256;          // 0..2047
        int r = idx >> 4, c4 = (idx & 15) * 4;
        float4 v = *(const float4*)(qkv + base + (size_t)(q0 + r) * C3 + qoff + c4);
        float* q = Qs + r * 68 + c4;
        q[0] = v.x * 0.125f; q[1] = v.y * 0.125f;
        q[2] = v.z * 0.125f; q[3] = v.w * 0.125f;
    }

    float m0 = -FLT_MAX, m1 = -FLT_MAX, l0 = 0.f, l1 = 0.f;
    float o[8][4] = {};

    for (int kt = 0; kt < SEQ; kt += 64) {
        __syncthreads();
        #pragma unroll
        for (int i = 0; i < 4; i++) {
            int idx = tid + i * 256;      // 0..1023
            int r = idx >> 4, c4 = (idx & 15) * 4;
            size_t gb = base + (size_t)(kt + r) * C3 + qoff;
            *(float4*)(Ks + r * 68 + c4) = *(const float4*)(qkv + gb + CDIM + c4);
            *(float4*)(Vs + r * 72 + c4) = *(const float4*)(qkv + gb + 2 * CDIM + c4);
        }
        if (tid < 64) msk[tid] = mask[bb * SEQ + kt + tid];
        __syncthreads();

        // ---- S = Q @ K^T (warp rows qrow..qrow+15, cols 0..63) ----
        float s[8][4] = {};
        #pragma unroll
        for (int ks = 0; ks < 64; ks += 8) {
            unsigned a[4];
            a[0] = __float_as_uint(Qs[(qrow + gr) * 68 + ks + kq]);
            a[1] = __float_as_uint(Qs[(qrow + gr + 8) * 68 + ks + kq]);
            a[2] = __float_as_uint(Qs[(qrow + gr) * 68 + ks + kq + 4]);
            a[3] = __float_as_uint(Qs[(qrow + gr + 8) * 68 + ks + kq + 4]);
            #pragma unroll
            for (int ni = 0; ni < 8; ni++) {
                unsigned b[2];
                int n = ni * 8 + gr;
                b[0] = __float_as_uint(Ks[n * 68 + ks + kq]);
                b[1] = __float_as_uint(Ks[n * 68 + ks + kq + 4]);
                MMA_TF32(s[ni], a, b);
            }
        }

        // ---- mask + online softmax (rows gr / gr+8; quad = same row) ----
        float mx0 = m0, mx1 = m1;
        #pragma unroll
        for (int ni = 0; ni < 8; ni++) {
            int t = ni * 8 + kq * 2;
            if (msk[t] == 0)     { s[ni][0] = -FLT_MAX; s[ni][2] = -FLT_MAX; }
            if (msk[t + 1] == 0) { s[ni][1] = -FLT_MAX; s[ni][3] = -FLT_MAX; }
            mx0 = fmaxf(mx0, fmaxf(s[ni][0], s[ni][1]));
            mx1 = fmaxf(mx1, fmaxf(s[ni][2], s[ni][3]));
        }
        mx0 = fmaxf(mx0, __shfl_xor_sync(0xffffffffu, mx0, 1));
        mx0 = fmaxf(mx0, __shfl_xor_sync(0xffffffffu, mx0, 2));
        mx1 = fmaxf(mx1, __shfl_xor_sync(0xffffffffu, mx1, 1));
        mx1 = fmaxf(mx1, __shfl_xor_sync(0xffffffffu, mx1, 2));

        float corr0 = __expf(m0 - mx0);
        float corr1 = __expf(m1 - mx1);
        m0 = mx0; m1 = mx1;

        float ls0 = 0.f, ls1 = 0.f;
        #pragma unroll
        for (int ni = 0; ni < 8; ni++) {
            float p00 = __expf(s[ni][0] - m0);
            float p01 = __expf(s[ni][1] - m0);
            float p10 = __expf(s[ni][2] - m1);
            float p11 = __expf(s[ni][3] - m1);
            ls0 += p00 + p01;
            ls1 += p10 + p11;
            int c = ni * 8 + kq * 2;
            *(float2*)(Ps + (qrow + gr) * 68 + c)     = make_float2(p00, p01);
            *(float2*)(Ps + (qrow + gr + 8) * 68 + c) = make_float2(p10, p11);
        }
        ls0 += __shfl_xor_sync(0xffffffffu, ls0, 1);
        ls0 += __shfl_xor_sync(0xffffffffu, ls0, 2);
        ls1 += __shfl_xor_sync(0xffffffffu, ls1, 1);
        ls1 += __shfl_xor_sync(0xffffffffu, ls1, 2);
        l0 = l0 * corr0 + ls0;
        l1 = l1 * corr1 + ls1;
        __syncwarp();

        // ---- O = O*corr + P @ V ----
        #pragma unroll
        for (int di = 0; di < 8; di++) {
            o[di][0] *= corr0; o[di][1] *= corr0;
            o[di][2] *= corr1; o[di][3] *= corr1;
        }
        #pragma unroll
        for (int ks = 0; ks < 64; ks += 8) {
            unsigned a[4];
            a[0] = __float_as_uint(Ps[(qrow + gr) * 68 + ks + kq]);
            a[1] = __float_as_uint(Ps[(qrow + gr + 8) * 68 + ks + kq]);
            a[2] = __float_as_uint(Ps[(qrow + gr) * 68 + ks + kq + 4]);
            a[3] = __float_as_uint(Ps[(qrow + gr + 8) * 68 + ks + kq + 4]);
            #pragma unroll
            for (int di = 0; di < 8; di++) {
                unsigned b[2];
                int n = di * 8 + gr;
                b[0] = __float_as_uint(Vs[(ks + kq) * 72 + n]);
                b[1] = __float_as_uint(Vs[(ks + kq + 4) * 72 + n]);
                MMA_TF32(o[di], a, b);
            }
        }
    }

    // ---- finalize + write ----
    float il0 = 1.0f / l0, il1 = 1.0f / l1;
    const int row0 = bb * SEQ + q0 + qrow + gr;
    #pragma unroll
    for (int di = 0; di < 8; di++) {
        int col = qoff + di * 8 + kq * 2;
        *(float2*)(out + (size_t)row0 * CDIM + col) =
            make_float2(o[di][0] * il0, o[di][1] * il0);
        *(float2*)(out + (size_t)(row0 + 8) * CDIM + col) =
            make_float2(o[di][2] * il1, o[di][3] * il1);
    }
}

// ---------------------------------------------------------------------------
// Launch
// ---------------------------------------------------------------------------
extern "C" void kernel_launch(void* const* d_in, const int* in_sizes, int n_in,
                              void* d_out, int out_size) {
    const float* x      = (const float*)d_in[0];
    const int*   mask   = (const int*)  d_in[1];
    const float* ln1_g  = (const float*)d_in[2];
    const float* ln1_b  = (const float*)d_in[3];
    const float* qkv_w  = (const float*)d_in[4];
    const float* qkv_b  = (const float*)d_in[5];
    const float* proj_w = (const float*)d_in[6];
    const float* proj_b = (const float*)d_in[7];
    const float* ln2_g  = (const float*)d_in[8];
    const float* ln2_b  = (const float*)d_in[9];
    const float* fc1_w  = (const float*)d_in[10];
    const float* fc1_b  = (const float*)d_in[11];
    const float* fc2_w  = (const float*)d_in[12];
    const float* fc2_b  = (const float*)d_in[13];
    float* out = (float*)d_out;

    float *p_ln, *p_qkv, *p_attn, *p_x1, *p_act;
    cudaGetSymbolAddress((void**)&p_ln,   g_ln);
    cudaGetSymbolAddress((void**)&p_qkv,  g_qkv);
    cudaGetSymbolAddress((void**)&p_attn, g_attn);
    cudaGetSymbolAddress((void**)&p_x1,   g_x1);
    cudaGetSymbolAddress((void**)&p_act,  g_act);

    cudaFuncSetAttribute(attn_tc, cudaFuncAttributeMaxDynamicSharedMemorySize,
                         ATT_SMEM);

    // 1) LN1
    layernorm_kernel<<<MROWS / 8, 256>>>(x, ln1_g, ln1_b, p_ln);

    // 2) QKV GEMM
    gemm_tc<false, false><<<dim3(C3 / 128, MROWS / 128), 256>>>(
        MROWS, C3, CDIM, p_ln, qkv_w, qkv_b, nullptr, p_qkv);

    // 3) fused attention (tensor core)
    attn_tc<<<dim3(SEQ / 128, 4 * NHEAD), 256, ATT_SMEM>>>(p_qkv, mask, p_attn);

    // 4) proj GEMM + residual
    gemm_tc<false, true><<<dim3(CDIM / 128, MROWS / 128), 256>>>(
        MROWS, CDIM, CDIM, p_attn, proj_w, proj_b, x, p_x1);

    // 5) LN2
    layernorm_kernel<<<MROWS / 8, 256>>>(p_x1, ln2_g, ln2_b, p_ln);

    // 6) FC1 + exact GELU
    gemm_tc<true, false><<<dim3(HID / 128, MROWS / 128), 256>>>(
        MROWS, HID, CDIM, p_ln, fc1_w, fc1_b, nullptr, p_act);

    // 7) FC2 + residual -> out
    gemm_tc<false, true><<<dim3(CDIM / 128, MROWS / 128), 256>>>(
        MROWS, CDIM, HID, p_act, fc2_w, fc2_b, p_x1, out);
}

// round 6
// speedup vs baseline: 3.9046x; 1.0727x over previous
#include <cuda_runtime.h>
#include <cuda_bf16.h>
#include <math.h>
#include <float.h>

// ---------------------------------------------------------------------------
// Problem constants: B=4, N=2048, C=768, H=12, D=64, MLP=3072
// ---------------------------------------------------------------------------
#define MROWS 8192          // B*N
#define CDIM  768
#define C3    2304
#define HID   3072
#define NHEAD 12
#define HDIM  64
#define SEQ   2048
#define LN_EPS 1e-6f

// ---------------------------------------------------------------------------
// Scratch (device globals; no allocation allowed)
// ---------------------------------------------------------------------------
__device__ float g_ln  [MROWS * CDIM];
__device__ float g_qkv [MROWS * C3];
__device__ float g_attn[MROWS * CDIM];
__device__ float g_x1  [MROWS * CDIM];
__device__ float g_act [MROWS * HID];

// ---------------------------------------------------------------------------
// helpers
// ---------------------------------------------------------------------------
#define MMA_TF32(d, a, b)                                                     \
    asm volatile(                                                             \
        "mma.sync.aligned.m16n8k8.row.col.f32.tf32.tf32.f32 "                 \
        "{%0,%1,%2,%3}, {%4,%5,%6,%7}, {%8,%9}, {%0,%1,%2,%3};\n"             \
        : "+f"(d[0]), "+f"(d[1]), "+f"(d[2]), "+f"(d[3])                      \
        : "r"(a[0]), "r"(a[1]), "r"(a[2]), "r"(a[3]), "r"(b[0]), "r"(b[1]))

__device__ __forceinline__ void cp16(void* dst, const void* src) {
    unsigned s = (unsigned)__cvta_generic_to_shared(dst);
    asm volatile("cp.async.cg.shared.global [%0], [%1], 16;\n" :: "r"(s), "l"(src));
}

// ---------------------------------------------------------------------------
// LayerNorm: warp per row, float4 everywhere. grid = MROWS/8, block 256.
// ---------------------------------------------------------------------------
__global__ void layernorm_kernel(const float* __restrict__ x,
                                 const float* __restrict__ g,
                                 const float* __restrict__ b,
                                 float* __restrict__ out) {
    const int row  = blockIdx.x * 8 + (threadIdx.x >> 5);
    const int lane = threadIdx.x & 31;
    const float* xr = x + (size_t)row * CDIM;

    float4 v[6];
    float s = 0.f;
    #pragma unroll
    for (int i = 0; i < 6; i++) {
        v[i] = *(const float4*)(xr + lane * 4 + i * 128);
        s += v[i].x + v[i].y + v[i].z + v[i].w;
    }
    #pragma unroll
    for (int o = 16; o > 0; o >>= 1) s += __shfl_xor_sync(0xffffffffu, s, o);
    float mu = s * (1.0f / CDIM);

    float s2 = 0.f;
    #pragma unroll
    for (int i = 0; i < 6; i++) {
        float dx = v[i].x - mu, dy = v[i].y - mu, dz = v[i].z - mu, dw = v[i].w - mu;
        s2 += dx * dx + dy * dy + dz * dz + dw * dw;
    }
    #pragma unroll
    for (int o = 16; o > 0; o >>= 1) s2 += __shfl_xor_sync(0xffffffffu, s2, o);
    float rs = rsqrtf(s2 * (1.0f / CDIM) + LN_EPS);

    float* orow = out + (size_t)row * CDIM;
    #pragma unroll
    for (int i = 0; i < 6; i++) {
        int c = lane * 4 + i * 128;
        float4 gg = *(const float4*)(g + c);
        float4 bb = *(const float4*)(b + c);
        float4 o4;
        o4.x = (v[i].x - mu) * rs * gg.x + bb.x;
        o4.y = (v[i].y - mu) * rs * gg.y + bb.y;
        o4.z = (v[i].z - mu) * rs * gg.z + bb.z;
        o4.w = (v[i].w - mu) * rs * gg.w + bb.w;
        *(float4*)(orow + c) = o4;
    }
}

// ---------------------------------------------------------------------------
// TF32 GEMM, cp.async double-buffered, BK=32 (halves barrier count vs BK=16).
// BM=BN=128, 256 threads (8 warps), warp tile 64x32 via m16n8k8.
// Dynamic smem 71.7KB: As [2][128][36] (m,k), Bs [2][32][136] (k,n).
// Fragment LDS banks: A (4*gr+kq)%32, B (8*kq+gr)%32 -> conflict-free.
// ---------------------------------------------------------------------------
#define BK32 32
#define A_STRIDE 36
#define B_STRIDE 136
#define A_BUF (128 * A_STRIDE)
#define B_BUF (BK32 * B_STRIDE)
#define GEMM_SMEM ((2 * A_BUF + 2 * B_BUF) * 4)

template<bool GELU, bool RES>
__global__ __launch_bounds__(256, 2)
void gemm_tc(int M, int N, int K,
             const float* __restrict__ A,
             const float* __restrict__ B,
             const float* __restrict__ bias,
             const float* __restrict__ res,
             float* __restrict__ C) {
    extern __shared__ float smg[];
    float* As = smg;                 // [2][128][A_STRIDE]
    float* Bs = smg + 2 * A_BUF;     // [2][32][B_STRIDE]

    const int tid  = threadIdx.x;
    const int lane = tid & 31;
    const int wid  = tid >> 5;
    const int gr   = lane >> 2;
    const int kq   = lane & 3;
    const int wm   = (wid >> 2) * 64;
    const int wn   = (wid & 3) * 32;

    const float* Ag = A + (size_t)blockIdx.y * 128 * K;
    const float* Bg = B + (size_t)blockIdx.x * 128;

    float acc[4][4][4] = {};

    auto load_tile = [&](int k0, int buf) {
        float* Ab = As + buf * A_BUF;
        float* Bb = Bs + buf * B_BUF;
        #pragma unroll
        for (int i = 0; i < 4; i++) {
            int ch = tid + i * 256;          // 0..1023
            int r  = ch >> 3;                // 0..127
            int c4 = (ch & 7) * 4;           // 0..28
            cp16(Ab + r * A_STRIDE + c4, Ag + (size_t)r * K + k0 + c4);
        }
        #pragma unroll
        for (int i = 0; i < 4; i++) {
            int ch = tid + i * 256;          // 0..1023
            int r  = ch >> 5;                // 0..31
            int c4 = (ch & 31) * 4;          // 0..124
            cp16(Bb + r * B_STRIDE + c4, Bg + (size_t)(k0 + r) * N + c4);
        }
        asm volatile("cp.async.commit_group;\n");
    };

    load_tile(0, 0);
    const int nt = K / BK32;
    for (int t = 0; t < nt; t++) {
        const int buf = t & 1;
        if (t + 1 < nt) {
            load_tile((t + 1) * BK32, buf ^ 1);
            asm volatile("cp.async.wait_group 1;\n");
        } else {
            asm volatile("cp.async.wait_group 0;\n");
        }
        __syncthreads();

        const float* Ab = As + buf * A_BUF;
        const float* Bb = Bs + buf * B_BUF;

        #pragma unroll
        for (int ks = 0; ks < BK32; ks += 8) {
            unsigned a[4][4], b[4][2];
            #pragma unroll
            for (int mi = 0; mi < 4; mi++) {
                int m = wm + mi * 16 + gr;
                a[mi][0] = __float_as_uint(Ab[m * A_STRIDE + ks + kq]);
                a[mi][1] = __float_as_uint(Ab[(m + 8) * A_STRIDE + ks + kq]);
                a[mi][2] = __float_as_uint(Ab[m * A_STRIDE + ks + kq + 4]);
                a[mi][3] = __float_as_uint(Ab[(m + 8) * A_STRIDE + ks + kq + 4]);
            }
            #pragma unroll
            for (int ni = 0; ni < 4; ni++) {
                int n = wn + ni * 8 + gr;
                b[ni][0] = __float_as_uint(Bb[(ks + kq) * B_STRIDE + n]);
                b[ni][1] = __float_as_uint(Bb[(ks + kq + 4) * B_STRIDE + n]);
            }
            #pragma unroll
            for (int mi = 0; mi < 4; mi++)
                #pragma unroll
                for (int ni = 0; ni < 4; ni++)
                    MMA_TF32(acc[mi][ni], a[mi], b[ni]);
        }
        __syncthreads();
    }

    #pragma unroll
    for (int mi = 0; mi < 4; mi++) {
        #pragma unroll
        for (int ni = 0; ni < 4; ni++) {
            int row = blockIdx.y * 128 + wm + mi * 16 + gr;
            int col = blockIdx.x * 128 + wn + ni * 8 + kq * 2;
            float2 bc = *(const float2*)(bias + col);
            #pragma unroll
            for (int h = 0; h < 2; h++) {
                int r = row + h * 8;
                float v0 = acc[mi][ni][h * 2 + 0] + bc.x;
                float v1 = acc[mi][ni][h * 2 + 1] + bc.y;
                if (GELU) {
                    v0 = 0.5f * v0 * (1.0f + erff(v0 * 0.70710678118654752f));
                    v1 = 0.5f * v1 * (1.0f + erff(v1 * 0.70710678118654752f));
                }
                if (RES) {
                    float2 rr = *(const float2*)(res + (size_t)r * N + col);
                    v0 += rr.x;
                    v1 += rr.y;
                }
                *(float2*)(C + (size_t)r * N + col) = make_float2(v0, v1);
            }
        }
    }
}

// ---------------------------------------------------------------------------
// Tensor-core flash attention. BQ=128 (warp owns 16 q-rows), BKV=64, D=64.
// TF32 m16n8k8 for S=Q@K^T and O+=P@V. Softmax state in registers
// (quad-shuffle reductions); P via warp-private SMEM. Dynamic smem ~103KB.
// ---------------------------------------------------------------------------
#define ATT_SMEM ((128 * 68 + 64 * 68 + 64 * 72 + 128 * 68) * 4 + 64 * 4)

__global__ __launch_bounds__(256, 1)
void attn_tc(const float* __restrict__ qkv,
             const int* __restrict__ mask,
             float* __restrict__ out) {
    extern __shared__ float sm[];
    float* Qs = sm;                       // [128][68]
    float* Ks = Qs + 128 * 68;            // [64][68]  (natural [t][d])
    float* Vs = Ks + 64 * 68;             // [64][72]  (natural [t][d])
    float* Ps = Vs + 64 * 72;             // [128][68]
    int*   msk = (int*)(Ps + 128 * 68);   // [64]

    const int tid  = threadIdx.x;
    const int lane = tid & 31;
    const int w    = tid >> 5;
    const int gr   = lane >> 2;
    const int kq   = lane & 3;
    const int bb   = blockIdx.y / NHEAD;
    const int hh   = blockIdx.y % NHEAD;
    const int q0   = blockIdx.x * 128;
    const size_t base = (size_t)bb * SEQ * C3;
    const int qoff = hh * HDIM;
    const int qrow = w * 16;

    // Q tile (pre-scaled by 1/sqrt(D))
    #pragma unroll
    for (int i = 0; i < 8; i++) {
        int idx = tid + i * 256;          // 0..2047
        int r = idx >> 4, c4 = (idx & 15) * 4;
        float4 v = *(const float4*)(qkv + base + (size_t)(q0 + r) * C3 + qoff + c4);
        float* q = Qs + r * 68 + c4;
        q[0] = v.x * 0.125f; q[1] = v.y * 0.125f;
        q[2] = v.z * 0.125f; q[3] = v.w * 0.125f;
    }

    float m0 = -FLT_MAX, m1 = -FLT_MAX, l0 = 0.f, l1 = 0.f;
    float o[8][4] = {};

    for (int kt = 0; kt < SEQ; kt += 64) {
        __syncthreads();
        #pragma unroll
        for (int i = 0; i < 4; i++) {
            int idx = tid + i * 256;      // 0..1023
            int r = idx >> 4, c4 = (idx & 15) * 4;
            size_t gb = base + (size_t)(kt + r) * C3 + qoff;
            *(float4*)(Ks + r * 68 + c4) = *(const float4*)(qkv + gb + CDIM + c4);
            *(float4*)(Vs + r * 72 + c4) = *(const float4*)(qkv + gb + 2 * CDIM + c4);
        }
        if (tid < 64) msk[tid] = mask[bb * SEQ + kt + tid];
        __syncthreads();

        // ---- S = Q @ K^T (warp rows qrow..qrow+15, cols 0..63) ----
        float s[8][4] = {};
        #pragma unroll
        for (int ks = 0; ks < 64; ks += 8) {
            unsigned a[4];
            a[0] = __float_as_uint(Qs[(qrow + gr) * 68 + ks + kq]);
            a[1] = __float_as_uint(Qs[(qrow + gr + 8) * 68 + ks + kq]);
            a[2] = __float_as_uint(Qs[(qrow + gr) * 68 + ks + kq + 4]);
            a[3] = __float_as_uint(Qs[(qrow + gr + 8) * 68 + ks + kq + 4]);
            #pragma unroll
            for (int ni = 0; ni < 8; ni++) {
                unsigned b[2];
                int n = ni * 8 + gr;
                b[0] = __float_as_uint(Ks[n * 68 + ks + kq]);
                b[1] = __float_as_uint(Ks[n * 68 + ks + kq + 4]);
                MMA_TF32(s[ni], a, b);
            }
        }

        // ---- mask + online softmax (rows gr / gr+8; quad = same row) ----
        float mx0 = m0, mx1 = m1;
        #pragma unroll
        for (int ni = 0; ni < 8; ni++) {
            int t = ni * 8 + kq * 2;
            if (msk[t] == 0)     { s[ni][0] = -FLT_MAX; s[ni][2] = -FLT_MAX; }
            if (msk[t + 1] == 0) { s[ni][1] = -FLT_MAX; s[ni][3] = -FLT_MAX; }
            mx0 = fmaxf(mx0, fmaxf(s[ni][0], s[ni][1]));
            mx1 = fmaxf(mx1, fmaxf(s[ni][2], s[ni][3]));
        }
        mx0 = fmaxf(mx0, __shfl_xor_sync(0xffffffffu, mx0, 1));
        mx0 = fmaxf(mx0, __shfl_xor_sync(0xffffffffu, mx0, 2));
        mx1 = fmaxf(mx1, __shfl_xor_sync(0xffffffffu, mx1, 1));
        mx1 = fmaxf(mx1, __shfl_xor_sync(0xffffffffu, mx1, 2));

        float corr0 = __expf(m0 - mx0);
        float corr1 = __expf(m1 - mx1);
        m0 = mx0; m1 = mx1;

        float ls0 = 0.f, ls1 = 0.f;
        #pragma unroll
        for (int ni = 0; ni < 8; ni++) {
            float p00 = __expf(s[ni][0] - m0);
            float p01 = __expf(s[ni][1] - m0);
            float p10 = __expf(s[ni][2] - m1);
            float p11 = __expf(s[ni][3] - m1);
            ls0 += p00 + p01;
            ls1 += p10 + p11;
            int c = ni * 8 + kq * 2;
            *(float2*)(Ps + (qrow + gr) * 68 + c)     = make_float2(p00, p01);
            *(float2*)(Ps + (qrow + gr + 8) * 68 + c) = make_float2(p10, p11);
        }
        ls0 += __shfl_xor_sync(0xffffffffu, ls0, 1);
        ls0 += __shfl_xor_sync(0xffffffffu, ls0, 2);
        ls1 += __shfl_xor_sync(0xffffffffu, ls1, 1);
        ls1 += __shfl_xor_sync(0xffffffffu, ls1, 2);
        l0 = l0 * corr0 + ls0;
        l1 = l1 * corr1 + ls1;
        __syncwarp();

        // ---- O = O*corr + P @ V ----
        #pragma unroll
        for (int di = 0; di < 8; di++) {
            o[di][0] *= corr0; o[di][1] *= corr0;
            o[di][2] *= corr1; o[di][3] *= corr1;
        }
        #pragma unroll
        for (int ks = 0; ks < 64; ks += 8) {
            unsigned a[4];
            a[0] = __float_as_uint(Ps[(qrow + gr) * 68 + ks + kq]);
            a[1] = __float_as_uint(Ps[(qrow + gr + 8) * 68 + ks + kq]);
            a[2] = __float_as_uint(Ps[(qrow + gr) * 68 + ks + kq + 4]);
            a[3] = __float_as_uint(Ps[(qrow + gr + 8) * 68 + ks + kq + 4]);
            #pragma unroll
            for (int di = 0; di < 8; di++) {
                unsigned b[2];
                int n = di * 8 + gr;
                b[0] = __float_as_uint(Vs[(ks + kq) * 72 + n]);
                b[1] = __float_as_uint(Vs[(ks + kq + 4) * 72 + n]);
                MMA_TF32(o[di], a, b);
            }
        }
    }

    // ---- finalize + write ----
    float il0 = 1.0f / l0, il1 = 1.0f / l1;
    const int row0 = bb * SEQ + q0 + qrow + gr;
    #pragma unroll
    for (int di = 0; di < 8; di++) {
        int col = qoff + di * 8 + kq * 2;
        *(float2*)(out + (size_t)row0 * CDIM + col) =
            make_float2(o[di][0] * il0, o[di][1] * il0);
        *(float2*)(out + (size_t)(row0 + 8) * CDIM + col) =
            make_float2(o[di][2] * il1, o[di][3] * il1);
    }
}

// ---------------------------------------------------------------------------
// Launch
// ---------------------------------------------------------------------------
extern "C" void kernel_launch(void* const* d_in, const int* in_sizes, int n_in,
                              void* d_out, int out_size) {
    const float* x      = (const float*)d_in[0];
    const int*   mask   = (const int*)  d_in[1];
    const float* ln1_g  = (const float*)d_in[2];
    const float* ln1_b  = (const float*)d_in[3];
    const float* qkv_w  = (const float*)d_in[4];
    const float* qkv_b  = (const float*)d_in[5];
    const float* proj_w = (const float*)d_in[6];
    const float* proj_b = (const float*)d_in[7];
    const float* ln2_g  = (const float*)d_in[8];
    const float* ln2_b  = (const float*)d_in[9];
    const float* fc1_w  = (const float*)d_in[10];
    const float* fc1_b  = (const float*)d_in[11];
    const float* fc2_w  = (const float*)d_in[12];
    const float* fc2_b  = (const float*)d_in[13];
    float* out = (float*)d_out;

    float *p_ln, *p_qkv, *p_attn, *p_x1, *p_act;
    cudaGetSymbolAddress((void**)&p_ln,   g_ln);
    cudaGetSymbolAddress((void**)&p_qkv,  g_qkv);
    cudaGetSymbolAddress((void**)&p_attn, g_attn);
    cudaGetSymbolAddress((void**)&p_x1,   g_x1);
    cudaGetSymbolAddress((void**)&p_act,  g_act);

    cudaFuncSetAttribute(attn_tc, cudaFuncAttributeMaxDynamicSharedMemorySize,
                         ATT_SMEM);
    cudaFuncSetAttribute(gemm_tc<false, false>,
                         cudaFuncAttributeMaxDynamicSharedMemorySize, GEMM_SMEM);
    cudaFuncSetAttribute(gemm_tc<false, true>,
                         cudaFuncAttributeMaxDynamicSharedMemorySize, GEMM_SMEM);
    cudaFuncSetAttribute(gemm_tc<true, false>,
                         cudaFuncAttributeMaxDynamicSharedMemorySize, GEMM_SMEM);

    // 1) LN1
    layernorm_kernel<<<MROWS / 8, 256>>>(x, ln1_g, ln1_b, p_ln);

    // 2) QKV GEMM
    gemm_tc<false, false><<<dim3(C3 / 128, MROWS / 128), 256, GEMM_SMEM>>>(
        MROWS, C3, CDIM, p_ln, qkv_w, qkv_b, nullptr, p_qkv);

    // 3) fused attention (tensor core)
    attn_tc<<<dim3(SEQ / 128, 4 * NHEAD), 256, ATT_SMEM>>>(p_qkv, mask, p_attn);

    // 4) proj GEMM + residual
    gemm_tc<false, true><<<dim3(CDIM / 128, MROWS / 128), 256, GEMM_SMEM>>>(
        MROWS, CDIM, CDIM, p_attn, proj_w, proj_b, x, p_x1);

    // 5) LN2
    layernorm_kernel<<<MROWS / 8, 256>>>(p_x1, ln2_g, ln2_b, p_ln);

    // 6) FC1 + exact GELU
    gemm_tc<true, false><<<dim3(HID / 128, MROWS / 128), 256, GEMM_SMEM>>>(
        MROWS, HID, CDIM, p_ln, fc1_w, fc1_b, nullptr, p_act);

    // 7) FC2 + residual -> out
    gemm_tc<false, true><<<dim3(CDIM / 128, MROWS / 128), 256, GEMM_SMEM>>>(
        MROWS, CDIM, HID, p_act, fc2_w, fc2_b, p_x1, out);
}

// round 7
// speedup vs baseline: 3.9626x; 1.0149x over previous
#include <cuda_runtime.h>
#include <cuda_bf16.h>
#include <math.h>
#include <float.h>

// ---------------------------------------------------------------------------
// Problem constants: B=4, N=2048, C=768, H=12, D=64, MLP=3072
// ---------------------------------------------------------------------------
#define MROWS 8192          // B*N
#define CDIM  768
#define C3    2304
#define HID   3072
#define NHEAD 12
#define HDIM  64
#define SEQ   2048
#define LN_EPS 1e-6f

// ---------------------------------------------------------------------------
// Scratch (device globals; no allocation allowed)
// ---------------------------------------------------------------------------
__device__ float g_ln  [MROWS * CDIM];
__device__ float g_qkv [MROWS * C3];
__device__ float g_attn[MROWS * CDIM];
__device__ float g_x1  [MROWS * CDIM];
__device__ float g_act [MROWS * HID];
// transposed weights ([N][K] layout)
__device__ float g_wqkv[CDIM * C3];
__device__ float g_wproj[CDIM * CDIM];
__device__ float g_wfc1[CDIM * HID];
__device__ float g_wfc2[HID * CDIM];

// ---------------------------------------------------------------------------
// helpers
// ---------------------------------------------------------------------------
#define MMA_TF32(d, a, b)                                                     \
    asm volatile(                                                             \
        "mma.sync.aligned.m16n8k8.row.col.f32.tf32.tf32.f32 "                 \
        "{%0,%1,%2,%3}, {%4,%5,%6,%7}, {%8,%9}, {%0,%1,%2,%3};\n"             \
        : "+f"(d[0]), "+f"(d[1]), "+f"(d[2]), "+f"(d[3])                      \
        : "r"(a[0]), "r"(a[1]), "r"(a[2]), "r"(a[3]), "r"(b[0]), "r"(b[1]))

#define LDSM4(r0, r1, r2, r3, addr)                                           \
    asm volatile("ldmatrix.sync.aligned.m8n8.x4.shared.b16 {%0,%1,%2,%3}, [%4];" \
        : "=r"(r0), "=r"(r1), "=r"(r2), "=r"(r3) : "r"(addr))

__device__ __forceinline__ void cp16(void* dst, const void* src) {
    unsigned s = (unsigned)__cvta_generic_to_shared(dst);
    asm volatile("cp.async.cg.shared.global [%0], [%1], 16;\n" :: "r"(s), "l"(src));
}

// ---------------------------------------------------------------------------
// Weight transpose: W[K][N] -> Wt[N][K]. 32x32 tiles, 256 threads.
// ---------------------------------------------------------------------------
__global__ void transpose_kernel(const float* __restrict__ in,
                                 float* __restrict__ outp, int K, int N) {
    __shared__ float t[32][33];
    const int kb = blockIdx.y * 32, nb = blockIdx.x * 32;
    const int tx = threadIdx.x & 31, ty = threadIdx.x >> 5;
    #pragma unroll
    for (int i = 0; i < 32; i += 8)
        t[ty + i][tx] = in[(size_t)(kb + ty + i) * N + nb + tx];
    __syncthreads();
    #pragma unroll
    for (int i = 0; i < 32; i += 8)
        outp[(size_t)(nb + ty + i) * K + kb + tx] = t[tx][ty + i];
}

// ---------------------------------------------------------------------------
// LayerNorm: warp per row, float4 everywhere. grid = MROWS/8, block 256.
// ---------------------------------------------------------------------------
__global__ void layernorm_kernel(const float* __restrict__ x,
                                 const float* __restrict__ g,
                                 const float* __restrict__ b,
                                 float* __restrict__ out) {
    const int row  = blockIdx.x * 8 + (threadIdx.x >> 5);
    const int lane = threadIdx.x & 31;
    const float* xr = x + (size_t)row * CDIM;

    float4 v[6];
    float s = 0.f;
    #pragma unroll
    for (int i = 0; i < 6; i++) {
        v[i] = *(const float4*)(xr + lane * 4 + i * 128);
        s += v[i].x + v[i].y + v[i].z + v[i].w;
    }
    #pragma unroll
    for (int o = 16; o > 0; o >>= 1) s += __shfl_xor_sync(0xffffffffu, s, o);
    float mu = s * (1.0f / CDIM);

    float s2 = 0.f;
    #pragma unroll
    for (int i = 0; i < 6; i++) {
        float dx = v[i].x - mu, dy = v[i].y - mu, dz = v[i].z - mu, dw = v[i].w - mu;
        s2 += dx * dx + dy * dy + dz * dz + dw * dw;
    }
    #pragma unroll
    for (int o = 16; o > 0; o >>= 1) s2 += __shfl_xor_sync(0xffffffffu, s2, o);
    float rs = rsqrtf(s2 * (1.0f / CDIM) + LN_EPS);

    float* orow = out + (size_t)row * CDIM;
    #pragma unroll
    for (int i = 0; i < 6; i++) {
        int c = lane * 4 + i * 128;
        float4 gg = *(const float4*)(g + c);
        float4 bb = *(const float4*)(b + c);
        float4 o4;
        o4.x = (v[i].x - mu) * rs * gg.x + bb.x;
        o4.y = (v[i].y - mu) * rs * gg.y + bb.y;
        o4.z = (v[i].z - mu) * rs * gg.z + bb.z;
        o4.w = (v[i].w - mu) * rs * gg.w + bb.w;
        *(float4*)(orow + c) = o4;
    }
}

// ---------------------------------------------------------------------------
// TF32 GEMM with ldmatrix fragment loads. Both operands K-contiguous:
// A[M][K] activations, Bt[N][K] pre-transposed weights. BM=BN=128, BK=32,
// 256 threads (8 warps, warp tile 64x32), cp.async double-buffered.
// SMEM: As/Bs [2][128][36]; stride 36 -> conflict-free LDSM (4-bank row step).
// Per k-8 step: 4 LDSM.x4 (A) + 2 LDSM.x4 (B) + 16 MMA (vs 24 scalar LDS before).
// ---------------------------------------------------------------------------
#define BK32 32
#define TSTRIDE 36
#define TILE_BUF (128 * TSTRIDE)
#define GEMM_SMEM (4 * TILE_BUF * 4)

template<bool GELU, bool RES>
__global__ __launch_bounds__(256, 2)
void gemm_tc(int M, int N, int K,
             const float* __restrict__ A,
             const float* __restrict__ Bt,
             const float* __restrict__ bias,
             const float* __restrict__ res,
             float* __restrict__ C) {
    extern __shared__ float smg[];
    float* As = smg;                  // [2][128][TSTRIDE]
    float* Bs = smg + 2 * TILE_BUF;   // [2][128][TSTRIDE]

    const int tid  = threadIdx.x;
    const int lane = tid & 31;
    const int wid  = tid >> 5;
    const int gr   = lane >> 2;
    const int kq   = lane & 3;
    const int grp  = lane >> 3;       // ldmatrix sub-matrix group 0..3
    const int wi   = lane & 7;        // row within group
    const int wm   = (wid >> 2) * 64;
    const int wn   = (wid & 3) * 32;

    const float* Ag = A  + (size_t)blockIdx.y * 128 * K;
    const float* Bg = Bt + (size_t)blockIdx.x * 128 * K;

    // ldmatrix per-thread base addresses (byte offsets into SMEM window)
    const unsigned a_base = (unsigned)__cvta_generic_to_shared(As)
        + ((wm + wi + ((grp & 1) << 3)) * TSTRIDE + ((grp >> 1) << 2)) * 4;
    const unsigned b_base = (unsigned)__cvta_generic_to_shared(Bs)
        + ((wn + wi + ((grp >> 1) << 3)) * TSTRIDE + ((grp & 1) << 2)) * 4;

    float acc[4][4][4] = {};

    auto load_tile = [&](int k0, int buf) {
        float* Ab = As + buf * TILE_BUF;
        float* Bb = Bs + buf * TILE_BUF;
        #pragma unroll
        for (int i = 0; i < 4; i++) {
            int ch = tid + i * 256;          // 0..1023
            int r  = ch >> 3;                // 0..127
            int c4 = (ch & 7) * 4;           // 0..28
            cp16(Ab + r * TSTRIDE + c4, Ag + (size_t)r * K + k0 + c4);
            cp16(Bb + r * TSTRIDE + c4, Bg + (size_t)r * K + k0 + c4);
        }
        asm volatile("cp.async.commit_group;\n");
    };

    load_tile(0, 0);
    const int nt = K / BK32;
    for (int t = 0; t < nt; t++) {
        const int buf = t & 1;
        if (t + 1 < nt) {
            load_tile((t + 1) * BK32, buf ^ 1);
            asm volatile("cp.async.wait_group 1;\n");
        } else {
            asm volatile("cp.async.wait_group 0;\n");
        }
        __syncthreads();

        const unsigned abuf = a_base + buf * TILE_BUF * 4;
        const unsigned bbuf = b_base + buf * TILE_BUF * 4;

        #pragma unroll
        for (int ks = 0; ks < BK32; ks += 8) {
            unsigned a[4][4], b[4][2];
            #pragma unroll
            for (int mi = 0; mi < 4; mi++)
                LDSM4(a[mi][0], a[mi][1], a[mi][2], a[mi][3],
                      abuf + (mi * 16 * TSTRIDE + ks) * 4);
            LDSM4(b[0][0], b[0][1], b[1][0], b[1][1], bbuf + ks * 4);
            LDSM4(b[2][0], b[2][1], b[3][0], b[3][1],
                  bbuf + (16 * TSTRIDE + ks) * 4);
            #pragma unroll
            for (int mi = 0; mi < 4; mi++)
                #pragma unroll
                for (int ni = 0; ni < 4; ni++)
                    MMA_TF32(acc[mi][ni], a[mi], b[ni]);
        }
        __syncthreads();
    }

    #pragma unroll
    for (int mi = 0; mi < 4; mi++) {
        #pragma unroll
        for (int ni = 0; ni < 4; ni++) {
            int row = blockIdx.y * 128 + wm + mi * 16 + gr;
            int col = blockIdx.x * 128 + wn + ni * 8 + kq * 2;
            float2 bc = *(const float2*)(bias + col);
            #pragma unroll
            for (int h = 0; h < 2; h++) {
                int r = row + h * 8;
                float v0 = acc[mi][ni][h * 2 + 0] + bc.x;
                float v1 = acc[mi][ni][h * 2 + 1] + bc.y;
                if (GELU) {
                    v0 = 0.5f * v0 * (1.0f + erff(v0 * 0.70710678118654752f));
                    v1 = 0.5f * v1 * (1.0f + erff(v1 * 0.70710678118654752f));
                }
                if (RES) {
                    float2 rr = *(const float2*)(res + (size_t)r * N + col);
                    v0 += rr.x;
                    v1 += rr.y;
                }
                *(float2*)(C + (size_t)r * N + col) = make_float2(v0, v1);
            }
        }
    }
}

// ---------------------------------------------------------------------------
// Tensor-core flash attention. BQ=128 (warp owns 16 q-rows), BKV=64, D=64.
// TF32 m16n8k8 for S=Q@K^T and O+=P@V. Softmax state in registers
// (quad-shuffle reductions); P via warp-private SMEM. Dynamic smem ~103KB.
// ---------------------------------------------------------------------------
#define ATT_SMEM ((128 * 68 + 64 * 68 + 64 * 72 + 128 * 68) * 4 + 64 * 4)

__global__ __launch_bounds__(256, 1)
void attn_tc(const float* __restrict__ qkv,
             const int* __restrict__ mask,
             float* __restrict__ out) {
    extern __shared__ float sm[];
    float* Qs = sm;                       // [128][68]
    float* Ks = Qs + 128 * 68;            // [64][68]  (natural [t][d])
    float* Vs = Ks + 64 * 68;             // [64][72]  (natural [t][d])
    float* Ps = Vs + 64 * 72;             // [128][68]
    int*   msk = (int*)(Ps + 128 * 68);   // [64]

    const int tid  = threadIdx.x;
    const int lane = tid & 31;
    const int w    = tid >> 5;
    const int gr   = lane >> 2;
    const int kq   = lane & 3;
    const int bb   = blockIdx.y / NHEAD;
    const int hh   = blockIdx.y % NHEAD;
    const int q0   = blockIdx.x * 128;
    const size_t base = (size_t)bb * SEQ * C3;
    const int qoff = hh * HDIM;
    const int qrow = w * 16;

    // Q tile (pre-scaled by 1/sqrt(D))
    #pragma unroll
    for (int i = 0; i < 8; i++) {
        int idx = tid + i * 256;          // 0..2047
        int r = idx >> 4, c4 = (idx & 15) * 4;
        float4 v = *(const float4*)(qkv + base + (size_t)(q0 + r) * C3 + qoff + c4);
        float* q = Qs + r * 68 + c4;
        q[0] = v.x * 0.125f; q[1] = v.y * 0.125f;
        q[2] = v.z * 0.125f; q[3] = v.w * 0.125f;
    }

    float m0 = -FLT_MAX, m1 = -FLT_MAX, l0 = 0.f, l1 = 0.f;
    float o[8][4] = {};

    for (int kt = 0; kt < SEQ; kt += 64) {
        __syncthreads();
        #pragma unroll
        for (int i = 0; i < 4; i++) {
            int idx = tid + i * 256;      // 0..1023
            int r = idx >> 4, c4 = (idx & 15) * 4;
            size_t gb = base + (size_t)(kt + r) * C3 + qoff;
            *(float4*)(Ks + r * 68 + c4) = *(const float4*)(qkv + gb + CDIM + c4);
            *(float4*)(Vs + r * 72 + c4) = *(const float4*)(qkv + gb + 2 * CDIM + c4);
        }
        if (tid < 64) msk[tid] = mask[bb * SEQ + kt + tid];
        __syncthreads();

        // ---- S = Q @ K^T (warp rows qrow..qrow+15, cols 0..63) ----
        float s[8][4] = {};
        #pragma unroll
        for (int ks = 0; ks < 64; ks += 8) {
            unsigned a[4];
            a[0] = __float_as_uint(Qs[(qrow + gr) * 68 + ks + kq]);
            a[1] = __float_as_uint(Qs[(qrow + gr + 8) * 68 + ks + kq]);
            a[2] = __float_as_uint(Qs[(qrow + gr) * 68 + ks + kq + 4]);
            a[3] = __float_as_uint(Qs[(qrow + gr + 8) * 68 + ks + kq + 4]);
            #pragma unroll
            for (int ni = 0; ni < 8; ni++) {
                unsigned b[2];
                int n = ni * 8 + gr;
                b[0] = __float_as_uint(Ks[n * 68 + ks + kq]);
                b[1] = __float_as_uint(Ks[n * 68 + ks + kq + 4]);
                MMA_TF32(s[ni], a, b);
            }
        }

        // ---- mask + online softmax (rows gr / gr+8; quad = same row) ----
        float mx0 = m0, mx1 = m1;
        #pragma unroll
        for (int ni = 0; ni < 8; ni++) {
            int t = ni * 8 + kq * 2;
            if (msk[t] == 0)     { s[ni][0] = -FLT_MAX; s[ni][2] = -FLT_MAX; }
            if (msk[t + 1] == 0) { s[ni][1] = -FLT_MAX; s[ni][3] = -FLT_MAX; }
            mx0 = fmaxf(mx0, fmaxf(s[ni][0], s[ni][1]));
            mx1 = fmaxf(mx1, fmaxf(s[ni][2], s[ni][3]));
        }
        mx0 = fmaxf(mx0, __shfl_xor_sync(0xffffffffu, mx0, 1));
        mx0 = fmaxf(mx0, __shfl_xor_sync(0xffffffffu, mx0, 2));
        mx1 = fmaxf(mx1, __shfl_xor_sync(0xffffffffu, mx1, 1));
        mx1 = fmaxf(mx1, __shfl_xor_sync(0xffffffffu, mx1, 2));

        float corr0 = __expf(m0 - mx0);
        float corr1 = __expf(m1 - mx1);
        m0 = mx0; m1 = mx1;

        float ls0 = 0.f, ls1 = 0.f;
        #pragma unroll
        for (int ni = 0; ni < 8; ni++) {
            float p00 = __expf(s[ni][0] - m0);
            float p01 = __expf(s[ni][1] - m0);
            float p10 = __expf(s[ni][2] - m1);
            float p11 = __expf(s[ni][3] - m1);
            ls0 += p00 + p01;
            ls1 += p10 + p11;
            int c = ni * 8 + kq * 2;
            *(float2*)(Ps + (qrow + gr) * 68 + c)     = make_float2(p00, p01);
            *(float2*)(Ps + (qrow + gr + 8) * 68 + c) = make_float2(p10, p11);
        }
        ls0 += __shfl_xor_sync(0xffffffffu, ls0, 1);
        ls0 += __shfl_xor_sync(0xffffffffu, ls0, 2);
        ls1 += __shfl_xor_sync(0xffffffffu, ls1, 1);
        ls1 += __shfl_xor_sync(0xffffffffu, ls1, 2);
        l0 = l0 * corr0 + ls0;
        l1 = l1 * corr1 + ls1;
        __syncwarp();

        // ---- O = O*corr + P @ V ----
        #pragma unroll
        for (int di = 0; di < 8; di++) {
            o[di][0] *= corr0; o[di][1] *= corr0;
            o[di][2] *= corr1; o[di][3] *= corr1;
        }
        #pragma unroll
        for (int ks = 0; ks < 64; ks += 8) {
            unsigned a[4];
            a[0] = __float_as_uint(Ps[(qrow + gr) * 68 + ks + kq]);
            a[1] = __float_as_uint(Ps[(qrow + gr + 8) * 68 + ks + kq]);
            a[2] = __float_as_uint(Ps[(qrow + gr) * 68 + ks + kq + 4]);
            a[3] = __float_as_uint(Ps[(qrow + gr + 8) * 68 + ks + kq + 4]);
            #pragma unroll
            for (int di = 0; di < 8; di++) {
                unsigned b[2];
                int n = di * 8 + gr;
                b[0] = __float_as_uint(Vs[(ks + kq) * 72 + n]);
                b[1] = __float_as_uint(Vs[(ks + kq + 4) * 72 + n]);
                MMA_TF32(o[di], a, b);
            }
        }
    }

    // ---- finalize + write ----
    float il0 = 1.0f / l0, il1 = 1.0f / l1;
    const int row0 = bb * SEQ + q0 + qrow + gr;
    #pragma unroll
    for (int di = 0; di < 8; di++) {
        int col = qoff + di * 8 + kq * 2;
        *(float2*)(out + (size_t)row0 * CDIM + col) =
            make_float2(o[di][0] * il0, o[di][1] * il0);
        *(float2*)(out + (size_t)(row0 + 8) * CDIM + col) =
            make_float2(o[di][2] * il1, o[di][3] * il1);
    }
}

// ---------------------------------------------------------------------------
// Launch
// ---------------------------------------------------------------------------
extern "C" void kernel_launch(void* const* d_in, const int* in_sizes, int n_in,
                              void* d_out, int out_size) {
    const float* x      = (const float*)d_in[0];
    const int*   mask   = (const int*)  d_in[1];
    const float* ln1_g  = (const float*)d_in[2];
    const float* ln1_b  = (const float*)d_in[3];
    const float* qkv_w  = (const float*)d_in[4];
    const float* qkv_b  = (const float*)d_in[5];
    const float* proj_w = (const float*)d_in[6];
    const float* proj_b = (const float*)d_in[7];
    const float* ln2_g  = (const float*)d_in[8];
    const float* ln2_b  = (const float*)d_in[9];
    const float* fc1_w  = (const float*)d_in[10];
    const float* fc1_b  = (const float*)d_in[11];
    const float* fc2_w  = (const float*)d_in[12];
    const float* fc2_b  = (const float*)d_in[13];
    float* out = (float*)d_out;

    float *p_ln, *p_qkv, *p_attn, *p_x1, *p_act;
    float *p_wqkv, *p_wproj, *p_wfc1, *p_wfc2;
    cudaGetSymbolAddress((void**)&p_ln,    g_ln);
    cudaGetSymbolAddress((void**)&p_qkv,   g_qkv);
    cudaGetSymbolAddress((void**)&p_attn,  g_attn);
    cudaGetSymbolAddress((void**)&p_x1,    g_x1);
    cudaGetSymbolAddress((void**)&p_act,   g_act);
    cudaGetSymbolAddress((void**)&p_wqkv,  g_wqkv);
    cudaGetSymbolAddress((void**)&p_wproj, g_wproj);
    cudaGetSymbolAddress((void**)&p_wfc1,  g_wfc1);
    cudaGetSymbolAddress((void**)&p_wfc2,  g_wfc2);

    cudaFuncSetAttribute(attn_tc, cudaFuncAttributeMaxDynamicSharedMemorySize,
                         ATT_SMEM);
    cudaFuncSetAttribute(gemm_tc<false, false>,
                         cudaFuncAttributeMaxDynamicSharedMemorySize, GEMM_SMEM);
    cudaFuncSetAttribute(gemm_tc<false, true>,
                         cudaFuncAttributeMaxDynamicSharedMemorySize, GEMM_SMEM);
    cudaFuncSetAttribute(gemm_tc<true, false>,
                         cudaFuncAttributeMaxDynamicSharedMemorySize, GEMM_SMEM);

    // 0) transpose weights to [N][K]
    transpose_kernel<<<dim3(C3 / 32, CDIM / 32), 256>>>(qkv_w, p_wqkv, CDIM, C3);
    transpose_kernel<<<dim3(CDIM / 32, CDIM / 32), 256>>>(proj_w, p_wproj, CDIM, CDIM);
    transpose_kernel<<<dim3(HID / 32, CDIM / 32), 256>>>(fc1_w, p_wfc1, CDIM, HID);
    transpose_kernel<<<dim3(CDIM / 32, HID / 32), 256>>>(fc2_w, p_wfc2, HID, CDIM);

    // 1) LN1
    layernorm_kernel<<<MROWS / 8, 256>>>(x, ln1_g, ln1_b, p_ln);

    // 2) QKV GEMM
    gemm_tc<false, false><<<dim3(C3 / 128, MROWS / 128), 256, GEMM_SMEM>>>(
        MROWS, C3, CDIM, p_ln, p_wqkv, qkv_b, nullptr, p_qkv);

    // 3) fused attention (tensor core)
    attn_tc<<<dim3(SEQ / 128, 4 * NHEAD), 256, ATT_SMEM>>>(p_qkv, mask, p_attn);

    // 4) proj GEMM + residual
    gemm_tc<false, true><<<dim3(CDIM / 128, MROWS / 128), 256, GEMM_SMEM>>>(
        MROWS, CDIM, CDIM, p_attn, p_wproj, proj_b, x, p_x1);

    // 5) LN2
    layernorm_kernel<<<MROWS / 8, 256>>>(p_x1, ln2_g, ln2_b, p_ln);

    // 6) FC1 + exact GELU
    gemm_tc<true, false><<<dim3(HID / 128, MROWS / 128), 256, GEMM_SMEM>>>(
        MROWS, HID, CDIM, p_ln, p_wfc1, fc1_b, nullptr, p_act);

    // 7) FC2 + residual -> out
    gemm_tc<false, true><<<dim3(CDIM / 128, MROWS / 128), 256, GEMM_SMEM>>>(
        MROWS, CDIM, HID, p_act, p_wfc2, fc2_b, p_x1, out);
}

// round 9
// speedup vs baseline: 5.4538x; 1.3763x over previous
#include <cuda_runtime.h>
#include <cuda_fp16.h>
#include <math.h>
#include <float.h>

// ---------------------------------------------------------------------------
// Problem constants: B=4, N=2048, C=768, H=12, D=64, MLP=3072
// ---------------------------------------------------------------------------
#define MROWS 8192          // B*N
#define CDIM  768
#define C3    2304
#define HID   3072
#define NHEAD 12
#define HDIM  64
#define SEQ   2048
#define LN_EPS 1e-6f

// ---------------------------------------------------------------------------
// Scratch (device globals; no allocation allowed)
// ---------------------------------------------------------------------------
__device__ __half g_ln  [MROWS * CDIM];   // LN out (GEMM A input)
__device__ float  g_qkv [MROWS * C3];     // QKV out (attention input)
__device__ __half g_attn[MROWS * CDIM];   // attention out (proj A input)
__device__ float  g_x1  [MROWS * CDIM];   // residual stream after attn
__device__ __half g_act [MROWS * HID];    // gelu(fc1) (FC2 A input)
// transposed fp16 weights ([N][K] layout)
__device__ __half g_wqkv [CDIM * C3];
__device__ __half g_wproj[CDIM * CDIM];
__device__ __half g_wfc1 [CDIM * HID];
__device__ __half g_wfc2 [HID * CDIM];

// ---------------------------------------------------------------------------
// helpers
// ---------------------------------------------------------------------------
#define MMA_TF32(d, a, b)                                                     \
    asm volatile(                                                             \
        "mma.sync.aligned.m16n8k8.row.col.f32.tf32.tf32.f32 "                 \
        "{%0,%1,%2,%3}, {%4,%5,%6,%7}, {%8,%9}, {%0,%1,%2,%3};\n"             \
        : "+f"(d[0]), "+f"(d[1]), "+f"(d[2]), "+f"(d[3])                      \
        : "r"(a[0]), "r"(a[1]), "r"(a[2]), "r"(a[3]), "r"(b[0]), "r"(b[1]))

#define MMA_F16(d, a, b)                                                      \
    asm volatile(                                                             \
        "mma.sync.aligned.m16n8k16.row.col.f32.f16.f16.f32 "                  \
        "{%0,%1,%2,%3}, {%4,%5,%6,%7}, {%8,%9}, {%0,%1,%2,%3};\n"             \
        : "+f"(d[0]), "+f"(d[1]), "+f"(d[2]), "+f"(d[3])                      \
        : "r"(a[0]), "r"(a[1]), "r"(a[2]), "r"(a[3]), "r"(b[0]), "r"(b[1]))

#define LDSM4(r0, r1, r2, r3, addr)                                           \
    asm volatile("ldmatrix.sync.aligned.m8n8.x4.shared.b16 {%0,%1,%2,%3}, [%4];" \
        : "=r"(r0), "=r"(r1), "=r"(r2), "=r"(r3) : "r"(addr))

__device__ __forceinline__ void cp16s(unsigned dst, const void* src) {
    asm volatile("cp.async.cg.shared.global [%0], [%1], 16;\n" :: "r"(dst), "l"(src));
}

// ---------------------------------------------------------------------------
// Weight transpose + fp16 convert: W[K][N] f32 -> Wt[N][K] f16. 32x32 tiles.
// ---------------------------------------------------------------------------
__global__ void transpose_h_kernel(const float* __restrict__ in,
                                   __half* __restrict__ outp, int K, int N) {
    __shared__ float t[32][33];
    const int kb = blockIdx.y * 32, nb = blockIdx.x * 32;
    const int tx = threadIdx.x & 31, ty = threadIdx.x >> 5;
    #pragma unroll
    for (int i = 0; i < 32; i += 8)
        t[ty + i][tx] = in[(size_t)(kb + ty + i) * N + nb + tx];
    __syncthreads();
    #pragma unroll
    for (int i = 0; i < 32; i += 8)
        outp[(size_t)(nb + ty + i) * K + kb + tx] = __float2half_rn(t[tx][ty + i]);
}

// ---------------------------------------------------------------------------
// LayerNorm: warp per row, fp16 output. grid = MROWS/8, block 256.
// ---------------------------------------------------------------------------
__global__ void layernorm_kernel(const float* __restrict__ x,
                                 const float* __restrict__ g,
                                 const float* __restrict__ b,
                                 __half* __restrict__ out) {
    const int row  = blockIdx.x * 8 + (threadIdx.x >> 5);
    const int lane = threadIdx.x & 31;
    const float* xr = x + (size_t)row * CDIM;

    float4 v[6];
    float s = 0.f;
    #pragma unroll
    for (int i = 0; i < 6; i++) {
        v[i] = *(const float4*)(xr + lane * 4 + i * 128);
        s += v[i].x + v[i].y + v[i].z + v[i].w;
    }
    #pragma unroll
    for (int o = 16; o > 0; o >>= 1) s += __shfl_xor_sync(0xffffffffu, s, o);
    float mu = s * (1.0f / CDIM);

    float s2 = 0.f;
    #pragma unroll
    for (int i = 0; i < 6; i++) {
        float dx = v[i].x - mu, dy = v[i].y - mu, dz = v[i].z - mu, dw = v[i].w - mu;
        s2 += dx * dx + dy * dy + dz * dz + dw * dw;
    }
    #pragma unroll
    for (int o = 16; o > 0; o >>= 1) s2 += __shfl_xor_sync(0xffffffffu, s2, o);
    float rs = rsqrtf(s2 * (1.0f / CDIM) + LN_EPS);

    __half* orow = out + (size_t)row * CDIM;
    #pragma unroll
    for (int i = 0; i < 6; i++) {
        int c = lane * 4 + i * 128;
        float4 gg = *(const float4*)(g + c);
        float4 bb = *(const float4*)(b + c);
        __half2 h0 = __floats2half2_rn((v[i].x - mu) * rs * gg.x + bb.x,
                                       (v[i].y - mu) * rs * gg.y + bb.y);
        __half2 h1 = __floats2half2_rn((v[i].z - mu) * rs * gg.z + bb.z,
                                       (v[i].w - mu) * rs * gg.w + bb.w);
        *(__half2*)(orow + c)     = h0;
        *(__half2*)(orow + c + 2) = h1;
    }
}

// ---------------------------------------------------------------------------
// FP16 GEMM (m16n8k16). A[M][K] f16, Bt[N][K] f16 (both K-contiguous).
// BM=BN=128, BK=64 halves, 256 threads (8 warps, warp tile 64x32),
// cp.async double-buffered. SMEM tiles [128][72] halves (stride 144B ->
// ldmatrix row step 36 banks = 4 mod 32: conflict-free).
// Per k16-step: 4 LDSM.x4 (A) + 2 LDSM.x4 (B) + 16 MMA. Per BK=64 iter:
// 24 LDSM + 64 MMA covering 2x the K of the old tf32 version.
// ---------------------------------------------------------------------------
#define BKH 64
#define TSH 72
#define TILE_H (128 * TSH)
#define GEMM_SMEM (4 * TILE_H * 2)

template<bool GELU, bool RES, bool OUTH>
__global__ __launch_bounds__(256, 2)
void gemm_f16(int M, int N, int K,
              const __half* __restrict__ A,
              const __half* __restrict__ Bt,
              const float* __restrict__ bias,
              const float* __restrict__ res,
              void* __restrict__ Cv) {
    extern __shared__ __half smh[];
    __half* As = smh;                  // [2][128][TSH]
    __half* Bs = smh + 2 * TILE_H;     // [2][128][TSH]

    const int tid  = threadIdx.x;
    const int lane = tid & 31;
    const int wid  = tid >> 5;
    const int gr   = lane >> 2;
    const int kq   = lane & 3;
    const int wm   = (wid >> 2) * 64;
    const int wn   = (wid & 3) * 32;

    const __half* Ag = A  + (size_t)blockIdx.y * 128 * K;
    const __half* Bg = Bt + (size_t)blockIdx.x * 128 * K;

    // ldmatrix per-thread base addresses (byte offsets)
    // A: lanes 0-7:(m0-7,k0) 8-15:(m8-15,k0) 16-23:(m0-7,k8) 24-31:(m8-15,k8)
    const unsigned a_base = (unsigned)__cvta_generic_to_shared(As)
        + ((wm + (lane & 7) + (((lane >> 3) & 1) << 3)) * TSH
           + ((lane >> 4) << 3)) * 2;
    // B: lanes 0-7:(n0-7,k0) 8-15:(n0-7,k8) 16-23:(n8-15,k0) 24-31:(n8-15,k8)
    const unsigned b_base = (unsigned)__cvta_generic_to_shared(Bs)
        + ((wn + (lane & 7) + ((lane >> 4) << 3)) * TSH
           + (((lane >> 3) & 1) << 3)) * 2;

    float acc[4][4][4] = {};

    auto load_tile = [&](int k0, int buf) {
        __half* Ab = As + buf * TILE_H;
        __half* Bb = Bs + buf * TILE_H;
        const unsigned Abs = (unsigned)__cvta_generic_to_shared(Ab);
        const unsigned Bbs = (unsigned)__cvta_generic_to_shared(Bb);
        #pragma unroll
        for (int i = 0; i < 4; i++) {
            int ch = tid + i * 256;          // 0..1023
            int r  = ch >> 3;                // 0..127
            int c  = ch & 7;                 // 16B chunk (8 halves)
            cp16s(Abs + (r * TSH + c * 8) * 2, Ag + (size_t)r * K + k0 + c * 8);
            cp16s(Bbs + (r * TSH + c * 8) * 2, Bg + (size_t)r * K + k0 + c * 8);
        }
        asm volatile("cp.async.commit_group;\n");
    };

    load_tile(0, 0);
    const int nt = K / BKH;
    for (int t = 0; t < nt; t++) {
        const int buf = t & 1;
        if (t + 1 < nt) {
            load_tile((t + 1) * BKH, buf ^ 1);
            asm volatile("cp.async.wait_group 1;\n");
        } else {
            asm volatile("cp.async.wait_group 0;\n");
        }
        __syncthreads();

        const unsigned abuf = a_base + buf * TILE_H * 2;
        const unsigned bbuf = b_base + buf * TILE_H * 2;

        #pragma unroll
        for (int j = 0; j < 4; j++) {        // k16 steps within BK=64
            unsigned a[4][4], b[4][2];
            #pragma unroll
            for (int mi = 0; mi < 4; mi++)
                LDSM4(a[mi][0], a[mi][1], a[mi][2], a[mi][3],
                      abuf + (mi * 16 * TSH) * 2 + j * 32);
            LDSM4(b[0][0], b[0][1], b[1][0], b[1][1], bbuf + j * 32);
            LDSM4(b[2][0], b[2][1], b[3][0], b[3][1],
                  bbuf + (16 * TSH) * 2 + j * 32);
            #pragma unroll
            for (int mi = 0; mi < 4; mi++)
                #pragma unroll
                for (int ni = 0; ni < 4; ni++)
                    MMA_F16(acc[mi][ni], a[mi], b[ni]);
        }
        __syncthreads();
    }

    float* Cf = (float*)Cv;
    __half* Ch = (__half*)Cv;
    #pragma unroll
    for (int mi = 0; mi < 4; mi++) {
        #pragma unroll
        for (int ni = 0; ni < 4; ni++) {
            int row = blockIdx.y * 128 + wm + mi * 16 + gr;
            int col = blockIdx.x * 128 + wn + ni * 8 + kq * 2;
            float2 bc = *(const float2*)(bias + col);
            #pragma unroll
            for (int h = 0; h < 2; h++) {
                int r = row + h * 8;
                float v0 = acc[mi][ni][h * 2 + 0] + bc.x;
                float v1 = acc[mi][ni][h * 2 + 1] + bc.y;
                if (GELU) {
                    v0 = 0.5f * v0 * (1.0f + erff(v0 * 0.70710678118654752f));
                    v1 = 0.5f * v1 * (1.0f + erff(v1 * 0.70710678118654752f));
                }
                if (RES) {
                    float2 rr = *(const float2*)(res + (size_t)r * N + col);
                    v0 += rr.x;
                    v1 += rr.y;
                }
                if (OUTH) {
                    *(__half2*)(Ch + (size_t)r * N + col) = __floats2half2_rn(v0, v1);
                } else {
                    *(float2*)(Cf + (size_t)r * N + col) = make_float2(v0, v1);
                }
            }
        }
    }
}

// ---------------------------------------------------------------------------
// Tensor-core flash attention (tf32 path, unchanged compute; fp16 output).
// BQ=128 (warp owns 16 q-rows), BKV=64, D=64. Dynamic smem ~103KB.
// ---------------------------------------------------------------------------
#define ATT_SMEM ((128 * 68 + 64 * 68 + 64 * 72 + 128 * 68) * 4 + 64 * 4)

__global__ __launch_bounds__(256, 1)
void attn_tc(const float* __restrict__ qkv,
             const int* __restrict__ mask,
             __half* __restrict__ out) {
    extern __shared__ float sm[];
    float* Qs = sm;                       // [128][68]
    float* Ks = Qs + 128 * 68;            // [64][68]
    float* Vs = Ks + 64 * 68;             // [64][72]
    float* Ps = Vs + 64 * 72;             // [128][68]
    int*   msk = (int*)(Ps + 128 * 68);   // [64]

    const int tid  = threadIdx.x;
    const int lane = tid & 31;
    const int w    = tid >> 5;
    const int gr   = lane >> 2;
    const int kq   = lane & 3;
    const int bb   = blockIdx.y / NHEAD;
    const int hh   = blockIdx.y % NHEAD;
    const int q0   = blockIdx.x * 128;
    const size_t base = (size_t)bb * SEQ * C3;
    const int qoff = hh * HDIM;
    const int qrow = w * 16;

    #pragma unroll
    for (int i = 0; i < 8; i++) {
        int idx = tid + i * 256;
        int r = idx >> 4, c4 = (idx & 15) * 4;
        float4 v = *(const float4*)(qkv + base + (size_t)(q0 + r) * C3 + qoff + c4);
        float* q = Qs + r * 68 + c4;
        q[0] = v.x * 0.125f; q[1] = v.y * 0.125f;
        q[2] = v.z * 0.125f; q[3] = v.w * 0.125f;
    }

    float m0 = -FLT_MAX, m1 = -FLT_MAX, l0 = 0.f, l1 = 0.f;
    float o[8][4] = {};

    for (int kt = 0; kt < SEQ; kt += 64) {
        __syncthreads();
        #pragma unroll
        for (int i = 0; i < 4; i++) {
            int idx = tid + i * 256;
            int r = idx >> 4, c4 = (idx & 15) * 4;
            size_t gb = base + (size_t)(kt + r) * C3 + qoff;
            *(float4*)(Ks + r * 68 + c4) = *(const float4*)(qkv + gb + CDIM + c4);
            *(float4*)(Vs + r * 72 + c4) = *(const float4*)(qkv + gb + 2 * CDIM + c4);
        }
        if (tid < 64) msk[tid] = mask[bb * SEQ + kt + tid];
        __syncthreads();

        float s[8][4] = {};
        #pragma unroll
        for (int ks = 0; ks < 64; ks += 8) {
            unsigned a[4];
            a[0] = __float_as_uint(Qs[(qrow + gr) * 68 + ks + kq]);
            a[1] = __float_as_uint(Qs[(qrow + gr + 8) * 68 + ks + kq]);
            a[2] = __float_as_uint(Qs[(qrow + gr) * 68 + ks + kq + 4]);
            a[3] = __float_as_uint(Qs[(qrow + gr + 8) * 68 + ks + kq + 4]);
            #pragma unroll
            for (int ni = 0; ni < 8; ni++) {
                unsigned b[2];
                int n = ni * 8 + gr;
                b[0] = __float_as_uint(Ks[n * 68 + ks + kq]);
                b[1] = __float_as_uint(Ks[n * 68 + ks + kq + 4]);
                MMA_TF32(s[ni], a, b);
            }
        }

        float mx0 = m0, mx1 = m1;
        #pragma unroll
        for (int ni = 0; ni < 8; ni++) {
            int t = ni * 8 + kq * 2;
            if (msk[t] == 0)     { s[ni][0] = -FLT_MAX; s[ni][2] = -FLT_MAX; }
            if (msk[t + 1] == 0) { s[ni][1] = -FLT_MAX; s[ni][3] = -FLT_MAX; }
            mx0 = fmaxf(mx0, fmaxf(s[ni][0], s[ni][1]));
            mx1 = fmaxf(mx1, fmaxf(s[ni][2], s[ni][3]));
        }
        mx0 = fmaxf(mx0, __shfl_xor_sync(0xffffffffu, mx0, 1));
        mx0 = fmaxf(mx0, __shfl_xor_sync(0xffffffffu, mx0, 2));
        mx1 = fmaxf(mx1, __shfl_xor_sync(0xffffffffu, mx1, 1));
        mx1 = fmaxf(mx1, __shfl_xor_sync(0xffffffffu, mx1, 2));

        float corr0 = __expf(m0 - mx0);
        float corr1 = __expf(m1 - mx1);
        m0 = mx0; m1 = mx1;

        float ls0 = 0.f, ls1 = 0.f;
        #pragma unroll
        for (int ni = 0; ni < 8; ni++) {
            float p00 = __expf(s[ni][0] - m0);
            float p01 = __expf(s[ni][1] - m0);
            float p10 = __expf(s[ni][2] - m1);
            float p11 = __expf(s[ni][3] - m1);
            ls0 += p00 + p01;
            ls1 += p10 + p11;
            int c = ni * 8 + kq * 2;
            *(float2*)(Ps + (qrow + gr) * 68 + c)     = make_float2(p00, p01);
            *(float2*)(Ps + (qrow + gr + 8) * 68 + c) = make_float2(p10, p11);
        }
        ls0 += __shfl_xor_sync(0xffffffffu, ls0, 1);
        ls0 += __shfl_xor_sync(0xffffffffu, ls0, 2);
        ls1 += __shfl_xor_sync(0xffffffffu, ls1, 1);
        ls1 += __shfl_xor_sync(0xffffffffu, ls1, 2);
        l0 = l0 * corr0 + ls0;
        l1 = l1 * corr1 + ls1;
        __syncwarp();

        #pragma unroll
        for (int di = 0; di < 8; di++) {
            o[di][0] *= corr0; o[di][1] *= corr0;
            o[di][2] *= corr1; o[di][3] *= corr1;
        }
        #pragma unroll
        for (int ks = 0; ks < 64; ks += 8) {
            unsigned a[4];
            a[0] = __float_as_uint(Ps[(qrow + gr) * 68 + ks + kq]);
            a[1] = __float_as_uint(Ps[(qrow + gr + 8) * 68 + ks + kq]);
            a[2] = __float_as_uint(Ps[(qrow + gr) * 68 + ks + kq + 4]);
            a[3] = __float_as_uint(Ps[(qrow + gr + 8) * 68 + ks + kq + 4]);
            #pragma unroll
            for (int di = 0; di < 8; di++) {
                unsigned b[2];
                int n = di * 8 + gr;
                b[0] = __float_as_uint(Vs[(ks + kq) * 72 + n]);
                b[1] = __float_as_uint(Vs[(ks + kq + 4) * 72 + n]);
                MMA_TF32(o[di], a, b);
            }
        }
    }

    float il0 = 1.0f / l0, il1 = 1.0f / l1;
    const int row0 = bb * SEQ + q0 + qrow + gr;
    #pragma unroll
    for (int di = 0; di < 8; di++) {
        int col = qoff + di * 8 + kq * 2;
        *(__half2*)(out + (size_t)row0 * CDIM + col) =
            __floats2half2_rn(o[di][0] * il0, o[di][1] * il0);
        *(__half2*)(out + (size_t)(row0 + 8) * CDIM + col) =
            __floats2half2_rn(o[di][2] * il1, o[di][3] * il1);
    }
}

// ---------------------------------------------------------------------------
// Launch
// ---------------------------------------------------------------------------
extern "C" void kernel_launch(void* const* d_in, const int* in_sizes, int n_in,
                              void* d_out, int out_size) {
    const float* x      = (const float*)d_in[0];
    const int*   mask   = (const int*)  d_in[1];
    const float* ln1_g  = (const float*)d_in[2];
    const float* ln1_b  = (const float*)d_in[3];
    const float* qkv_w  = (const float*)d_in[4];
    const float* qkv_b  = (const float*)d_in[5];
    const float* proj_w = (const float*)d_in[6];
    const float* proj_b = (const float*)d_in[7];
    const float* ln2_g  = (const float*)d_in[8];
    const float* ln2_b  = (const float*)d_in[9];
    const float* fc1_w  = (const float*)d_in[10];
    const float* fc1_b  = (const float*)d_in[11];
    const float* fc2_w  = (const float*)d_in[12];
    const float* fc2_b  = (const float*)d_in[13];
    float* out = (float*)d_out;

    __half *p_ln, *p_attn, *p_act, *p_wqkv, *p_wproj, *p_wfc1, *p_wfc2;
    float  *p_qkv, *p_x1;
    cudaGetSymbolAddress((void**)&p_ln,    g_ln);
    cudaGetSymbolAddress((void**)&p_qkv,   g_qkv);
    cudaGetSymbolAddress((void**)&p_attn,  g_attn);
    cudaGetSymbolAddress((void**)&p_x1,    g_x1);
    cudaGetSymbolAddress((void**)&p_act,   g_act);
    cudaGetSymbolAddress((void**)&p_wqkv,  g_wqkv);
    cudaGetSymbolAddress((void**)&p_wproj, g_wproj);
    cudaGetSymbolAddress((void**)&p_wfc1,  g_wfc1);
    cudaGetSymbolAddress((void**)&p_wfc2,  g_wfc2);

    cudaFuncSetAttribute(attn_tc, cudaFuncAttributeMaxDynamicSharedMemorySize,
                         ATT_SMEM);
    cudaFuncSetAttribute(gemm_f16<false, false, false>,
                         cudaFuncAttributeMaxDynamicSharedMemorySize, GEMM_SMEM);
    cudaFuncSetAttribute(gemm_f16<false, true, false>,
                         cudaFuncAttributeMaxDynamicSharedMemorySize, GEMM_SMEM);
    cudaFuncSetAttribute(gemm_f16<true, false, true>,
                         cudaFuncAttributeMaxDynamicSharedMemorySize, GEMM_SMEM);

    // 0) transpose + fp16-convert weights to [N][K]
    transpose_h_kernel<<<dim3(C3 / 32, CDIM / 32), 256>>>(qkv_w, p_wqkv, CDIM, C3);
    transpose_h_kernel<<<dim3(CDIM / 32, CDIM / 32), 256>>>(proj_w, p_wproj, CDIM, CDIM);
    transpose_h_kernel<<<dim3(HID / 32, CDIM / 32), 256>>>(fc1_w, p_wfc1, CDIM, HID);
    transpose_h_kernel<<<dim3(CDIM / 32, HID / 32), 256>>>(fc2_w, p_wfc2, HID, CDIM);

    // 1) LN1 (fp16 out)
    layernorm_kernel<<<MROWS / 8, 256>>>(x, ln1_g, ln1_b, p_ln);

    // 2) QKV GEMM (fp16 in, fp32 out)
    gemm_f16<false, false, false><<<dim3(C3 / 128, MROWS / 128), 256, GEMM_SMEM>>>(
        MROWS, C3, CDIM, p_ln, p_wqkv, qkv_b, nullptr, p_qkv);

    // 3) fused attention (fp32 in, fp16 out)
    attn_tc<<<dim3(SEQ / 128, 4 * NHEAD), 256, ATT_SMEM>>>(p_qkv, mask, p_attn);

    // 4) proj GEMM + residual (fp32 out)
    gemm_f16<false, true, false><<<dim3(CDIM / 128, MROWS / 128), 256, GEMM_SMEM>>>(
        MROWS, CDIM, CDIM, p_attn, p_wproj, proj_b, x, p_x1);

    // 5) LN2 (fp16 out)
    layernorm_kernel<<<MROWS / 8, 256>>>(p_x1, ln2_g, ln2_b, p_ln);

    // 6) FC1 + exact GELU (fp16 out)
    gemm_f16<true, false, true><<<dim3(HID / 128, MROWS / 128), 256, GEMM_SMEM>>>(
        MROWS, HID, CDIM, p_ln, p_wfc1, fc1_b, nullptr, p_act);

    // 7) FC2 + residual -> out (fp32)
    gemm_f16<false, true, false><<<dim3(CDIM / 128, MROWS / 128), 256, GEMM_SMEM>>>(
        MROWS, CDIM, HID, p_act, p_wfc2, fc2_b, p_x1, out);
}

// round 10
// speedup vs baseline: 7.4113x; 1.3589x over previous
#include <cuda_runtime.h>
#include <cuda_fp16.h>
#include <math.h>
#include <float.h>

// ---------------------------------------------------------------------------
// Problem constants: B=4, N=2048, C=768, H=12, D=64, MLP=3072
// ---------------------------------------------------------------------------
#define MROWS 8192          // B*N
#define CDIM  768
#define C3    2304
#define HID   3072
#define NHEAD 12
#define HDIM  64
#define SEQ   2048
#define LN_EPS 1e-6f

// ---------------------------------------------------------------------------
// Scratch (device globals; no allocation allowed)
// ---------------------------------------------------------------------------
__device__ __half g_ln  [MROWS * CDIM];   // LN out (GEMM A input)
__device__ __half g_qkv [MROWS * C3];     // QKV out fp16 (attention input)
__device__ __half g_attn[MROWS * CDIM];   // attention out (proj A input)
__device__ float  g_x1  [MROWS * CDIM];   // residual stream after attn
__device__ __half g_act [MROWS * HID];    // gelu(fc1) (FC2 A input)
// transposed fp16 weights ([N][K] layout)
__device__ __half g_wqkv [CDIM * C3];
__device__ __half g_wproj[CDIM * CDIM];
__device__ __half g_wfc1 [CDIM * HID];
__device__ __half g_wfc2 [HID * CDIM];

// ---------------------------------------------------------------------------
// helpers
// ---------------------------------------------------------------------------
#define MMA_F16(d, a, b)                                                      \
    asm volatile(                                                             \
        "mma.sync.aligned.m16n8k16.row.col.f32.f16.f16.f32 "                  \
        "{%0,%1,%2,%3}, {%4,%5,%6,%7}, {%8,%9}, {%0,%1,%2,%3};\n"             \
        : "+f"(d[0]), "+f"(d[1]), "+f"(d[2]), "+f"(d[3])                      \
        : "r"(a[0]), "r"(a[1]), "r"(a[2]), "r"(a[3]), "r"(b[0]), "r"(b[1]))

#define LDSM4(r0, r1, r2, r3, addr)                                           \
    asm volatile("ldmatrix.sync.aligned.m8n8.x4.shared.b16 {%0,%1,%2,%3}, [%4];" \
        : "=r"(r0), "=r"(r1), "=r"(r2), "=r"(r3) : "r"(addr))

#define LDSM4T(r0, r1, r2, r3, addr)                                          \
    asm volatile("ldmatrix.sync.aligned.m8n8.x4.trans.shared.b16 {%0,%1,%2,%3}, [%4];" \
        : "=r"(r0), "=r"(r1), "=r"(r2), "=r"(r3) : "r"(addr))

__device__ __forceinline__ void cp16s(unsigned dst, const void* src) {
    asm volatile("cp.async.cg.shared.global [%0], [%1], 16;\n" :: "r"(dst), "l"(src));
}

// ---------------------------------------------------------------------------
// Weight transpose + fp16 convert: W[K][N] f32 -> Wt[N][K] f16. 32x32 tiles.
// ---------------------------------------------------------------------------
__global__ void transpose_h_kernel(const float* __restrict__ in,
                                   __half* __restrict__ outp, int K, int N) {
    __shared__ float t[32][33];
    const int kb = blockIdx.y * 32, nb = blockIdx.x * 32;
    const int tx = threadIdx.x & 31, ty = threadIdx.x >> 5;
    #pragma unroll
    for (int i = 0; i < 32; i += 8)
        t[ty + i][tx] = in[(size_t)(kb + ty + i) * N + nb + tx];
    __syncthreads();
    #pragma unroll
    for (int i = 0; i < 32; i += 8)
        outp[(size_t)(nb + ty + i) * K + kb + tx] = __float2half_rn(t[tx][ty + i]);
}

// ---------------------------------------------------------------------------
// LayerNorm: warp per row, fp16 output. grid = MROWS/8, block 256.
// ---------------------------------------------------------------------------
__global__ void layernorm_kernel(const float* __restrict__ x,
                                 const float* __restrict__ g,
                                 const float* __restrict__ b,
                                 __half* __restrict__ out) {
    const int row  = blockIdx.x * 8 + (threadIdx.x >> 5);
    const int lane = threadIdx.x & 31;
    const float* xr = x + (size_t)row * CDIM;

    float4 v[6];
    float s = 0.f;
    #pragma unroll
    for (int i = 0; i < 6; i++) {
        v[i] = *(const float4*)(xr + lane * 4 + i * 128);
        s += v[i].x + v[i].y + v[i].z + v[i].w;
    }
    #pragma unroll
    for (int o = 16; o > 0; o >>= 1) s += __shfl_xor_sync(0xffffffffu, s, o);
    float mu = s * (1.0f / CDIM);

    float s2 = 0.f;
    #pragma unroll
    for (int i = 0; i < 6; i++) {
        float dx = v[i].x - mu, dy = v[i].y - mu, dz = v[i].z - mu, dw = v[i].w - mu;
        s2 += dx * dx + dy * dy + dz * dz + dw * dw;
    }
    #pragma unroll
    for (int o = 16; o > 0; o >>= 1) s2 += __shfl_xor_sync(0xffffffffu, s2, o);
    float rs = rsqrtf(s2 * (1.0f / CDIM) + LN_EPS);

    __half* orow = out + (size_t)row * CDIM;
    #pragma unroll
    for (int i = 0; i < 6; i++) {
        int c = lane * 4 + i * 128;
        float4 gg = *(const float4*)(g + c);
        float4 bb = *(const float4*)(b + c);
        __half2 h0 = __floats2half2_rn((v[i].x - mu) * rs * gg.x + bb.x,
                                       (v[i].y - mu) * rs * gg.y + bb.y);
        __half2 h1 = __floats2half2_rn((v[i].z - mu) * rs * gg.z + bb.z,
                                       (v[i].w - mu) * rs * gg.w + bb.w);
        *(__half2*)(orow + c)     = h0;
        *(__half2*)(orow + c + 2) = h1;
    }
}

// ---------------------------------------------------------------------------
// FP16 GEMM (m16n8k16). A[M][K] f16, Bt[N][K] f16 (both K-contiguous).
// BM=BN=128, BK=64 halves, 256 threads (8 warps, warp tile 64x32),
// cp.async double-buffered. SMEM tiles [128][72] halves.
// ---------------------------------------------------------------------------
#define BKH 64
#define TSH 72
#define TILE_H (128 * TSH)
#define GEMM_SMEM (4 * TILE_H * 2)

template<bool GELU, bool RES, bool OUTH>
__global__ __launch_bounds__(256, 2)
void gemm_f16(int M, int N, int K,
              const __half* __restrict__ A,
              const __half* __restrict__ Bt,
              const float* __restrict__ bias,
              const float* __restrict__ res,
              void* __restrict__ Cv) {
    extern __shared__ __half smh[];
    __half* As = smh;                  // [2][128][TSH]
    __half* Bs = smh + 2 * TILE_H;     // [2][128][TSH]

    const int tid  = threadIdx.x;
    const int lane = tid & 31;
    const int wid  = tid >> 5;
    const int gr   = lane >> 2;
    const int kq   = lane & 3;
    const int wm   = (wid >> 2) * 64;
    const int wn   = (wid & 3) * 32;

    const __half* Ag = A  + (size_t)blockIdx.y * 128 * K;
    const __half* Bg = Bt + (size_t)blockIdx.x * 128 * K;

    const unsigned a_base = (unsigned)__cvta_generic_to_shared(As)
        + ((wm + (lane & 7) + (((lane >> 3) & 1) << 3)) * TSH
           + ((lane >> 4) << 3)) * 2;
    const unsigned b_base = (unsigned)__cvta_generic_to_shared(Bs)
        + ((wn + (lane & 7) + ((lane >> 4) << 3)) * TSH
           + (((lane >> 3) & 1) << 3)) * 2;

    float acc[4][4][4] = {};

    auto load_tile = [&](int k0, int buf) {
        const unsigned Abs = (unsigned)__cvta_generic_to_shared(As + buf * TILE_H);
        const unsigned Bbs = (unsigned)__cvta_generic_to_shared(Bs + buf * TILE_H);
        #pragma unroll
        for (int i = 0; i < 4; i++) {
            int ch = tid + i * 256;
            int r  = ch >> 3;
            int c  = ch & 7;
            cp16s(Abs + (r * TSH + c * 8) * 2, Ag + (size_t)r * K + k0 + c * 8);
            cp16s(Bbs + (r * TSH + c * 8) * 2, Bg + (size_t)r * K + k0 + c * 8);
        }
        asm volatile("cp.async.commit_group;\n");
    };

    load_tile(0, 0);
    const int nt = K / BKH;
    for (int t = 0; t < nt; t++) {
        const int buf = t & 1;
        if (t + 1 < nt) {
            load_tile((t + 1) * BKH, buf ^ 1);
            asm volatile("cp.async.wait_group 1;\n");
        } else {
            asm volatile("cp.async.wait_group 0;\n");
        }
        __syncthreads();

        const unsigned abuf = a_base + buf * TILE_H * 2;
        const unsigned bbuf = b_base + buf * TILE_H * 2;

        #pragma unroll
        for (int j = 0; j < 4; j++) {
            unsigned a[4][4], b[4][2];
            #pragma unroll
            for (int mi = 0; mi < 4; mi++)
                LDSM4(a[mi][0], a[mi][1], a[mi][2], a[mi][3],
                      abuf + (mi * 16 * TSH) * 2 + j * 32);
            LDSM4(b[0][0], b[0][1], b[1][0], b[1][1], bbuf + j * 32);
            LDSM4(b[2][0], b[2][1], b[3][0], b[3][1],
                  bbuf + (16 * TSH) * 2 + j * 32);
            #pragma unroll
            for (int mi = 0; mi < 4; mi++)
                #pragma unroll
                for (int ni = 0; ni < 4; ni++)
                    MMA_F16(acc[mi][ni], a[mi], b[ni]);
        }
        __syncthreads();
    }

    float* Cf = (float*)Cv;
    __half* Ch = (__half*)Cv;
    #pragma unroll
    for (int mi = 0; mi < 4; mi++) {
        #pragma unroll
        for (int ni = 0; ni < 4; ni++) {
            int row = blockIdx.y * 128 + wm + mi * 16 + gr;
            int col = blockIdx.x * 128 + wn + ni * 8 + kq * 2;
            float2 bc = *(const float2*)(bias + col);
            #pragma unroll
            for (int h = 0; h < 2; h++) {
                int r = row + h * 8;
                float v0 = acc[mi][ni][h * 2 + 0] + bc.x;
                float v1 = acc[mi][ni][h * 2 + 1] + bc.y;
                if (GELU) {
                    v0 = 0.5f * v0 * (1.0f + erff(v0 * 0.70710678118654752f));
                    v1 = 0.5f * v1 * (1.0f + erff(v1 * 0.70710678118654752f));
                }
                if (RES) {
                    float2 rr = *(const float2*)(res + (size_t)r * N + col);
                    v0 += rr.x;
                    v1 += rr.y;
                }
                if (OUTH) {
                    *(__half2*)(Ch + (size_t)r * N + col) = __floats2half2_rn(v0, v1);
                } else {
                    *(float2*)(Cf + (size_t)r * N + col) = make_float2(v0, v1);
                }
            }
        }
    }
}

// ---------------------------------------------------------------------------
// FP16 tensor-core flash attention. BQ=128 (warp owns 16 q-rows), BKV=64.
// S=Q@K^T and O+=P@V via m16n8k16 + ldmatrix (V via ldmatrix.trans from
// natural [t][d] layout). Softmax stats fp32 in registers; P fp16 in
// warp-private SMEM. SMEM ~54.5KB -> 2 CTAs/SM.
// ---------------------------------------------------------------------------
#define ATTH_SMEM ((128 * 72 + 64 * 72 + 64 * 72 + 128 * 72) * 2 + 64 * 4)

__global__ __launch_bounds__(256, 2)
void attn_f16(const __half* __restrict__ qkv,
              const int* __restrict__ mask,
              __half* __restrict__ out) {
    extern __shared__ __half smh[];
    __half* Qs = smh;                  // [128][72]
    __half* Ks = Qs + 128 * 72;        // [64][72]  natural [t][d]
    __half* Vs = Ks + 64 * 72;         // [64][72]  natural [t][d]
    __half* Ps = Vs + 64 * 72;         // [128][72]
    int*   msk = (int*)(Ps + 128 * 72);

    const int tid  = threadIdx.x;
    const int lane = tid & 31;
    const int w    = tid >> 5;
    const int gr   = lane >> 2;
    const int kq   = lane & 3;
    const int bb   = blockIdx.y / NHEAD;
    const int hh   = blockIdx.y % NHEAD;
    const int q0   = blockIdx.x * 128;
    const size_t base = (size_t)bb * SEQ * C3;
    const int qoff = hh * HDIM;
    const int qrow = w * 16;

    const int l7 = lane & 7, l8 = (lane >> 3) & 1, l16 = (lane >> 4) & 1;
    // ldmatrix base addresses (bytes)
    const unsigned qs_b = (unsigned)__cvta_generic_to_shared(Qs)
        + ((qrow + l7 + l8 * 8) * 72 + l16 * 8) * 2;
    const unsigned ks_b = (unsigned)__cvta_generic_to_shared(Ks)
        + ((l7 + l16 * 8) * 72 + l8 * 8) * 2;
    const unsigned vs_b = (unsigned)__cvta_generic_to_shared(Vs)
        + ((l7 + l8 * 8) * 72 + l16 * 8) * 2;
    const unsigned ps_b = (unsigned)__cvta_generic_to_shared(Ps)
        + ((qrow + l7 + l8 * 8) * 72 + l16 * 8) * 2;
    const unsigned qs_s = (unsigned)__cvta_generic_to_shared(Qs);
    const unsigned ks_s = (unsigned)__cvta_generic_to_shared(Ks);
    const unsigned vs_s = (unsigned)__cvta_generic_to_shared(Vs);

    // load Q tile (fp16, no pre-scale; 1/8 applied to S)
    #pragma unroll
    for (int i = 0; i < 4; i++) {
        int ch = tid + i * 256;           // 0..1023
        int r = ch >> 3, c = ch & 7;
        cp16s(qs_s + (r * 72 + c * 8) * 2,
              qkv + base + (size_t)(q0 + r) * C3 + qoff + c * 8);
    }
    asm volatile("cp.async.commit_group;\n");

    float m0 = -FLT_MAX, m1 = -FLT_MAX, l0 = 0.f, l1 = 0.f;
    float o[8][4] = {};

    for (int kt = 0; kt < SEQ; kt += 64) {
        __syncthreads();                  // protect Ks/Vs/Ps reuse
        #pragma unroll
        for (int i = 0; i < 2; i++) {
            int ch = tid + i * 256;       // 0..511
            int r = ch >> 3, c = ch & 7;
            size_t gb = base + (size_t)(kt + r) * C3 + qoff;
            cp16s(ks_s + (r * 72 + c * 8) * 2, qkv + gb + CDIM + c * 8);
            cp16s(vs_s + (r * 72 + c * 8) * 2, qkv + gb + 2 * CDIM + c * 8);
        }
        if (tid < 64) msk[tid] = mask[bb * SEQ + kt + tid];
        asm volatile("cp.async.commit_group;\n");
        asm volatile("cp.async.wait_group 0;\n");
        __syncthreads();

        // ---- S = Q @ K^T ----
        float s[8][4] = {};
        #pragma unroll
        for (int ks = 0; ks < 64; ks += 16) {
            unsigned a[4], b[8][2];
            LDSM4(a[0], a[1], a[2], a[3], qs_b + ks * 2);
            #pragma unroll
            for (int g = 0; g < 4; g++)
                LDSM4(b[2 * g][0], b[2 * g][1], b[2 * g + 1][0], b[2 * g + 1][1],
                      ks_b + (g * 16 * 72) * 2 + ks * 2);
            #pragma unroll
            for (int ni = 0; ni < 8; ni++)
                MMA_F16(s[ni], a, b[ni]);
        }

        // ---- scale + mask + online softmax ----
        float mx0 = m0, mx1 = m1;
        #pragma unroll
        for (int ni = 0; ni < 8; ni++) {
            int t = ni * 8 + kq * 2;
            s[ni][0] *= 0.125f; s[ni][1] *= 0.125f;
            s[ni][2] *= 0.125f; s[ni][3] *= 0.125f;
            if (msk[t] == 0)     { s[ni][0] = -FLT_MAX; s[ni][2] = -FLT_MAX; }
            if (msk[t + 1] == 0) { s[ni][1] = -FLT_MAX; s[ni][3] = -FLT_MAX; }
            mx0 = fmaxf(mx0, fmaxf(s[ni][0], s[ni][1]));
            mx1 = fmaxf(mx1, fmaxf(s[ni][2], s[ni][3]));
        }
        mx0 = fmaxf(mx0, __shfl_xor_sync(0xffffffffu, mx0, 1));
        mx0 = fmaxf(mx0, __shfl_xor_sync(0xffffffffu, mx0, 2));
        mx1 = fmaxf(mx1, __shfl_xor_sync(0xffffffffu, mx1, 1));
        mx1 = fmaxf(mx1, __shfl_xor_sync(0xffffffffu, mx1, 2));

        float corr0 = __expf(m0 - mx0);
        float corr1 = __expf(m1 - mx1);
        m0 = mx0; m1 = mx1;

        float ls0 = 0.f, ls1 = 0.f;
        #pragma unroll
        for (int ni = 0; ni < 8; ni++) {
            float p00 = __expf(s[ni][0] - m0);
            float p01 = __expf(s[ni][1] - m0);
            float p10 = __expf(s[ni][2] - m1);
            float p11 = __expf(s[ni][3] - m1);
            ls0 += p00 + p01;
            ls1 += p10 + p11;
            int c = ni * 8 + kq * 2;
            *(__half2*)(Ps + (qrow + gr) * 72 + c)     = __floats2half2_rn(p00, p01);
            *(__half2*)(Ps + (qrow + gr + 8) * 72 + c) = __floats2half2_rn(p10, p11);
        }
        ls0 += __shfl_xor_sync(0xffffffffu, ls0, 1);
        ls0 += __shfl_xor_sync(0xffffffffu, ls0, 2);
        ls1 += __shfl_xor_sync(0xffffffffu, ls1, 1);
        ls1 += __shfl_xor_sync(0xffffffffu, ls1, 2);
        l0 = l0 * corr0 + ls0;
        l1 = l1 * corr1 + ls1;
        __syncwarp();                     // Ps rows are warp-private

        // ---- O = O*corr + P @ V ----
        #pragma unroll
        for (int di = 0; di < 8; di++) {
            o[di][0] *= corr0; o[di][1] *= corr0;
            o[di][2] *= corr1; o[di][3] *= corr1;
        }
        #pragma unroll
        for (int ks = 0; ks < 64; ks += 16) {
            unsigned a[4], b[8][2];
            LDSM4(a[0], a[1], a[2], a[3], ps_b + ks * 2);
            #pragma unroll
            for (int g = 0; g < 4; g++)
                LDSM4T(b[2 * g][0], b[2 * g][1], b[2 * g + 1][0], b[2 * g + 1][1],
                       vs_b + (ks * 72 + g * 16) * 2);
            #pragma unroll
            for (int di = 0; di < 8; di++)
                MMA_F16(o[di], a, b[di]);
        }
    }

    // ---- finalize + write fp16 ----
    float il0 = 1.0f / l0, il1 = 1.0f / l1;
    const int row0 = bb * SEQ + q0 + qrow + gr;
    #pragma unroll
    for (int di = 0; di < 8; di++) {
        int col = qoff + di * 8 + kq * 2;
        *(__half2*)(out + (size_t)row0 * CDIM + col) =
            __floats2half2_rn(o[di][0] * il0, o[di][1] * il0);
        *(__half2*)(out + (size_t)(row0 + 8) * CDIM + col) =
            __floats2half2_rn(o[di][2] * il1, o[di][3] * il1);
    }
}

// ---------------------------------------------------------------------------
// Launch
// ---------------------------------------------------------------------------
extern "C" void kernel_launch(void* const* d_in, const int* in_sizes, int n_in,
                              void* d_out, int out_size) {
    const float* x      = (const float*)d_in[0];
    const int*   mask   = (const int*)  d_in[1];
    const float* ln1_g  = (const float*)d_in[2];
    const float* ln1_b  = (const float*)d_in[3];
    const float* qkv_w  = (const float*)d_in[4];
    const float* qkv_b  = (const float*)d_in[5];
    const float* proj_w = (const float*)d_in[6];
    const float* proj_b = (const float*)d_in[7];
    const float* ln2_g  = (const float*)d_in[8];
    const float* ln2_b  = (const float*)d_in[9];
    const float* fc1_w  = (const float*)d_in[10];
    const float* fc1_b  = (const float*)d_in[11];
    const float* fc2_w  = (const float*)d_in[12];
    const float* fc2_b  = (const float*)d_in[13];
    float* out = (float*)d_out;

    __half *p_ln, *p_qkv, *p_attn, *p_act, *p_wqkv, *p_wproj, *p_wfc1, *p_wfc2;
    float  *p_x1;
    cudaGetSymbolAddress((void**)&p_ln,    g_ln);
    cudaGetSymbolAddress((void**)&p_qkv,   g_qkv);
    cudaGetSymbolAddress((void**)&p_attn,  g_attn);
    cudaGetSymbolAddress((void**)&p_x1,    g_x1);
    cudaGetSymbolAddress((void**)&p_act,   g_act);
    cudaGetSymbolAddress((void**)&p_wqkv,  g_wqkv);
    cudaGetSymbolAddress((void**)&p_wproj, g_wproj);
    cudaGetSymbolAddress((void**)&p_wfc1,  g_wfc1);
    cudaGetSymbolAddress((void**)&p_wfc2,  g_wfc2);

    cudaFuncSetAttribute(attn_f16, cudaFuncAttributeMaxDynamicSharedMemorySize,
                         ATTH_SMEM);
    cudaFuncSetAttribute(gemm_f16<false, false, true>,
                         cudaFuncAttributeMaxDynamicSharedMemorySize, GEMM_SMEM);
    cudaFuncSetAttribute(gemm_f16<false, true, false>,
                         cudaFuncAttributeMaxDynamicSharedMemorySize, GEMM_SMEM);
    cudaFuncSetAttribute(gemm_f16<true, false, true>,
                         cudaFuncAttributeMaxDynamicSharedMemorySize, GEMM_SMEM);

    // 0) transpose + fp16-convert weights to [N][K]
    transpose_h_kernel<<<dim3(C3 / 32, CDIM / 32), 256>>>(qkv_w, p_wqkv, CDIM, C3);
    transpose_h_kernel<<<dim3(CDIM / 32, CDIM / 32), 256>>>(proj_w, p_wproj, CDIM, CDIM);
    transpose_h_kernel<<<dim3(HID / 32, CDIM / 32), 256>>>(fc1_w, p_wfc1, CDIM, HID);
    transpose_h_kernel<<<dim3(CDIM / 32, HID / 32), 256>>>(fc2_w, p_wfc2, HID, CDIM);

    // 1) LN1 (fp16 out)
    layernorm_kernel<<<MROWS / 8, 256>>>(x, ln1_g, ln1_b, p_ln);

    // 2) QKV GEMM (fp16 out)
    gemm_f16<false, false, true><<<dim3(C3 / 128, MROWS / 128), 256, GEMM_SMEM>>>(
        MROWS, C3, CDIM, p_ln, p_wqkv, qkv_b, nullptr, p_qkv);

    // 3) fused attention (fp16 in/out)
    attn_f16<<<dim3(SEQ / 128, 4 * NHEAD), 256, ATTH_SMEM>>>(p_qkv, mask, p_attn);

    // 4) proj GEMM + residual (fp32 out)
    gemm_f16<false, true, false><<<dim3(CDIM / 128, MROWS / 128), 256, GEMM_SMEM>>>(
        MROWS, CDIM, CDIM, p_attn, p_wproj, proj_b, x, p_x1);

    // 5) LN2 (fp16 out)
    layernorm_kernel<<<MROWS / 8, 256>>>(p_x1, ln2_g, ln2_b, p_ln);

    // 6) FC1 + exact GELU (fp16 out)
    gemm_f16<true, false, true><<<dim3(HID / 128, MROWS / 128), 256, GEMM_SMEM>>>(
        MROWS, HID, CDIM, p_ln, p_wfc1, fc1_b, nullptr, p_act);

    // 7) FC2 + residual -> out (fp32)
    gemm_f16<false, true, false><<<dim3(CDIM / 128, MROWS / 128), 256, GEMM_SMEM>>>(
        MROWS, CDIM, HID, p_act, p_wfc2, fc2_b, p_x1, out);
}

// round 11
// speedup vs baseline: 7.6672x; 1.0345x over previous
#include <cuda_runtime.h>
#include <cuda_fp16.h>
#include <math.h>
#include <float.h>

// ---------------------------------------------------------------------------
// Problem constants: B=4, N=2048, C=768, H=12, D=64, MLP=3072
// ---------------------------------------------------------------------------
#define MROWS 8192          // B*N
#define CDIM  768
#define C3    2304
#define HID   3072
#define NHEAD 12
#define HDIM  64
#define SEQ   2048
#define LN_EPS 1e-6f

// ---------------------------------------------------------------------------
// Scratch (device globals; no allocation allowed)
// ---------------------------------------------------------------------------
__device__ __half g_ln  [MROWS * CDIM];
__device__ __half g_qkv [MROWS * C3];
__device__ __half g_attn[MROWS * CDIM];
__device__ float  g_x1  [MROWS * CDIM];
__device__ __half g_act [MROWS * HID];
__device__ __half g_wqkv [CDIM * C3];
__device__ __half g_wproj[CDIM * CDIM];
__device__ __half g_wfc1 [CDIM * HID];
__device__ __half g_wfc2 [HID * CDIM];

// ---------------------------------------------------------------------------
// helpers
// ---------------------------------------------------------------------------
#define MMA_F16(d, a, b)                                                      \
    asm volatile(                                                             \
        "mma.sync.aligned.m16n8k16.row.col.f32.f16.f16.f32 "                  \
        "{%0,%1,%2,%3}, {%4,%5,%6,%7}, {%8,%9}, {%0,%1,%2,%3};\n"             \
        : "+f"(d[0]), "+f"(d[1]), "+f"(d[2]), "+f"(d[3])                      \
        : "r"(a[0]), "r"(a[1]), "r"(a[2]), "r"(a[3]), "r"(b[0]), "r"(b[1]))

#define LDSM4(r0, r1, r2, r3, addr)                                           \
    asm volatile("ldmatrix.sync.aligned.m8n8.x4.shared.b16 {%0,%1,%2,%3}, [%4];" \
        : "=r"(r0), "=r"(r1), "=r"(r2), "=r"(r3) : "r"(addr))

#define LDSM4T(r0, r1, r2, r3, addr)                                          \
    asm volatile("ldmatrix.sync.aligned.m8n8.x4.trans.shared.b16 {%0,%1,%2,%3}, [%4];" \
        : "=r"(r0), "=r"(r1), "=r"(r2), "=r"(r3) : "r"(addr))

__device__ __forceinline__ void cp16s(unsigned dst, const void* src) {
    asm volatile("cp.async.cg.shared.global [%0], [%1], 16;\n" :: "r"(dst), "l"(src));
}

// ---------------------------------------------------------------------------
// Weight transpose + fp16 convert: W[K][N] f32 -> Wt[N][K] f16. 32x32 tiles.
// ---------------------------------------------------------------------------
__global__ void transpose_h_kernel(const float* __restrict__ in,
                                   __half* __restrict__ outp, int K, int N) {
    __shared__ float t[32][33];
    const int kb = blockIdx.y * 32, nb = blockIdx.x * 32;
    const int tx = threadIdx.x & 31, ty = threadIdx.x >> 5;
    #pragma unroll
    for (int i = 0; i < 32; i += 8)
        t[ty + i][tx] = in[(size_t)(kb + ty + i) * N + nb + tx];
    __syncthreads();
    #pragma unroll
    for (int i = 0; i < 32; i += 8)
        outp[(size_t)(nb + ty + i) * K + kb + tx] = __float2half_rn(t[tx][ty + i]);
}

// ---------------------------------------------------------------------------
// LayerNorm: warp per row, fp16 output. grid = MROWS/8, block 256.
// ---------------------------------------------------------------------------
__global__ void layernorm_kernel(const float* __restrict__ x,
                                 const float* __restrict__ g,
                                 const float* __restrict__ b,
                                 __half* __restrict__ out) {
    const int row  = blockIdx.x * 8 + (threadIdx.x >> 5);
    const int lane = threadIdx.x & 31;
    const float* xr = x + (size_t)row * CDIM;

    float4 v[6];
    float s = 0.f;
    #pragma unroll
    for (int i = 0; i < 6; i++) {
        v[i] = *(const float4*)(xr + lane * 4 + i * 128);
        s += v[i].x + v[i].y + v[i].z + v[i].w;
    }
    #pragma unroll
    for (int o = 16; o > 0; o >>= 1) s += __shfl_xor_sync(0xffffffffu, s, o);
    float mu = s * (1.0f / CDIM);

    float s2 = 0.f;
    #pragma unroll
    for (int i = 0; i < 6; i++) {
        float dx = v[i].x - mu, dy = v[i].y - mu, dz = v[i].z - mu, dw = v[i].w - mu;
        s2 += dx * dx + dy * dy + dz * dz + dw * dw;
    }
    #pragma unroll
    for (int o = 16; o > 0; o >>= 1) s2 += __shfl_xor_sync(0xffffffffu, s2, o);
    float rs = rsqrtf(s2 * (1.0f / CDIM) + LN_EPS);

    __half* orow = out + (size_t)row * CDIM;
    #pragma unroll
    for (int i = 0; i < 6; i++) {
        int c = lane * 4 + i * 128;
        float4 gg = *(const float4*)(g + c);
        float4 bb = *(const float4*)(b + c);
        __half2 h0 = __floats2half2_rn((v[i].x - mu) * rs * gg.x + bb.x,
                                       (v[i].y - mu) * rs * gg.y + bb.y);
        __half2 h1 = __floats2half2_rn((v[i].z - mu) * rs * gg.z + bb.z,
                                       (v[i].w - mu) * rs * gg.w + bb.w);
        *(__half2*)(orow + c)     = h0;
        *(__half2*)(orow + c + 2) = h1;
    }
}

// ---------------------------------------------------------------------------
// FP16 GEMM (m16n8k16), 3-stage cp.async pipeline, ONE barrier per K-iter.
// A[M][K] f16, Bt[N][K] f16. BM=BN=128, BK=64 halves, 8 warps (64x32 tiles).
// SMEM: 3 stages x (A,B) x [128][72] halves = 108KB; 2 CTAs/SM.
// ---------------------------------------------------------------------------
#define BKH 64
#define TSH 72
#define TILE_H (128 * TSH)
#define GEMM_SMEM (6 * TILE_H * 2)

template<bool GELU, bool RES, bool OUTH>
__global__ __launch_bounds__(256, 2)
void gemm_f16(int M, int N, int K,
              const __half* __restrict__ A,
              const __half* __restrict__ Bt,
              const float* __restrict__ bias,
              const float* __restrict__ res,
              void* __restrict__ Cv) {
    extern __shared__ __half smh[];
    __half* As = smh;                  // [3][128][TSH]
    __half* Bs = smh + 3 * TILE_H;     // [3][128][TSH]

    const int tid  = threadIdx.x;
    const int lane = tid & 31;
    const int wid  = tid >> 5;
    const int gr   = lane >> 2;
    const int kq   = lane & 3;
    const int wm   = (wid >> 2) * 64;
    const int wn   = (wid & 3) * 32;

    const __half* Ag = A  + (size_t)blockIdx.y * 128 * K;
    const __half* Bg = Bt + (size_t)blockIdx.x * 128 * K;

    const unsigned a_base = (unsigned)__cvta_generic_to_shared(As)
        + ((wm + (lane & 7) + (((lane >> 3) & 1) << 3)) * TSH
           + ((lane >> 4) << 3)) * 2;
    const unsigned b_base = (unsigned)__cvta_generic_to_shared(Bs)
        + ((wn + (lane & 7) + ((lane >> 4) << 3)) * TSH
           + (((lane >> 3) & 1) << 3)) * 2;

    float acc[4][4][4] = {};

    auto load_tile = [&](int k0, int st) {
        const unsigned Abs = (unsigned)__cvta_generic_to_shared(As + st * TILE_H);
        const unsigned Bbs = (unsigned)__cvta_generic_to_shared(Bs + st * TILE_H);
        #pragma unroll
        for (int i = 0; i < 4; i++) {
            int ch = tid + i * 256;
            int r  = ch >> 3;
            int c  = ch & 7;
            cp16s(Abs + (r * TSH + c * 8) * 2, Ag + (size_t)r * K + k0 + c * 8);
            cp16s(Bbs + (r * TSH + c * 8) * 2, Bg + (size_t)r * K + k0 + c * 8);
        }
        asm volatile("cp.async.commit_group;\n");
    };

    load_tile(0, 0);
    load_tile(BKH, 1);
    const int nt = K / BKH;
    int buf = 0, slot = 2;
    for (int t = 0; t < nt; t++) {
        if (t + 1 < nt) asm volatile("cp.async.wait_group 1;\n");
        else            asm volatile("cp.async.wait_group 0;\n");
        __syncthreads();

        if (t + 2 < nt) {
            load_tile((t + 2) * BKH, slot);
            slot = (slot + 1 == 3) ? 0 : slot + 1;
        }

        const unsigned abuf = a_base + buf * TILE_H * 2;
        const unsigned bbuf = b_base + buf * TILE_H * 2;

        #pragma unroll
        for (int j = 0; j < 4; j++) {
            unsigned a[4][4], b[4][2];
            #pragma unroll
            for (int mi = 0; mi < 4; mi++)
                LDSM4(a[mi][0], a[mi][1], a[mi][2], a[mi][3],
                      abuf + (mi * 16 * TSH) * 2 + j * 32);
            LDSM4(b[0][0], b[0][1], b[1][0], b[1][1], bbuf + j * 32);
            LDSM4(b[2][0], b[2][1], b[3][0], b[3][1],
                  bbuf + (16 * TSH) * 2 + j * 32);
            #pragma unroll
            for (int mi = 0; mi < 4; mi++)
                #pragma unroll
                for (int ni = 0; ni < 4; ni++)
                    MMA_F16(acc[mi][ni], a[mi], b[ni]);
        }
        buf = (buf + 1 == 3) ? 0 : buf + 1;
    }

    float* Cf = (float*)Cv;
    __half* Ch = (__half*)Cv;
    #pragma unroll
    for (int mi = 0; mi < 4; mi++) {
        #pragma unroll
        for (int ni = 0; ni < 4; ni++) {
            int row = blockIdx.y * 128 + wm + mi * 16 + gr;
            int col = blockIdx.x * 128 + wn + ni * 8 + kq * 2;
            float2 bc = *(const float2*)(bias + col);
            #pragma unroll
            for (int h = 0; h < 2; h++) {
                int r = row + h * 8;
                float v0 = acc[mi][ni][h * 2 + 0] + bc.x;
                float v1 = acc[mi][ni][h * 2 + 1] + bc.y;
                if (GELU) {
                    v0 = 0.5f * v0 * (1.0f + erff(v0 * 0.70710678118654752f));
                    v1 = 0.5f * v1 * (1.0f + erff(v1 * 0.70710678118654752f));
                }
                if (RES) {
                    float2 rr = *(const float2*)(res + (size_t)r * N + col);
                    v0 += rr.x;
                    v1 += rr.y;
                }
                if (OUTH) {
                    *(__half2*)(Ch + (size_t)r * N + col) = __floats2half2_rn(v0, v1);
                } else {
                    *(float2*)(Cf + (size_t)r * N + col) = make_float2(v0, v1);
                }
            }
        }
    }
}

// ---------------------------------------------------------------------------
// FP16 flash attention, 3-stage KV pipeline, ONE barrier per KV-iter.
// BQ=128 (warp owns 16 q-rows), BKV=64. SMEM ~91KB -> 2 CTAs/SM.
// ---------------------------------------------------------------------------
#define KSTAGE (64 * 72)   // halves per K (or V) stage
#define ATTH_SMEM ((128 * 72 + 3 * KSTAGE + 3 * KSTAGE + 128 * 72) * 2 + 3 * 64 * 4)
#define NKT (SEQ / 64)

__global__ __launch_bounds__(256, 2)
void attn_f16(const __half* __restrict__ qkv,
              const int* __restrict__ mask,
              __half* __restrict__ out) {
    extern __shared__ __half smh[];
    __half* Qs = smh;                      // [128][72]
    __half* Ks = Qs + 128 * 72;            // [3][64][72]
    __half* Vs = Ks + 3 * KSTAGE;          // [3][64][72]
    __half* Ps = Vs + 3 * KSTAGE;          // [128][72]
    int   (*msk)[64] = (int(*)[64])(Ps + 128 * 72);   // [3][64]

    const int tid  = threadIdx.x;
    const int lane = tid & 31;
    const int w    = tid >> 5;
    const int gr   = lane >> 2;
    const int kq   = lane & 3;
    const int bb   = blockIdx.y / NHEAD;
    const int hh   = blockIdx.y % NHEAD;
    const int q0   = blockIdx.x * 128;
    const size_t base = (size_t)bb * SEQ * C3;
    const int qoff = hh * HDIM;
    const int qrow = w * 16;

    const int l7 = lane & 7, l8 = (lane >> 3) & 1, l16 = (lane >> 4) & 1;
    const unsigned qs_b = (unsigned)__cvta_generic_to_shared(Qs)
        + ((qrow + l7 + l8 * 8) * 72 + l16 * 8) * 2;
    const unsigned ks_b = (unsigned)__cvta_generic_to_shared(Ks)
        + ((l7 + l16 * 8) * 72 + l8 * 8) * 2;
    const unsigned vs_b = (unsigned)__cvta_generic_to_shared(Vs)
        + ((l7 + l8 * 8) * 72 + l16 * 8) * 2;
    const unsigned ps_b = (unsigned)__cvta_generic_to_shared(Ps)
        + ((qrow + l7 + l8 * 8) * 72 + l16 * 8) * 2;
    const unsigned qs_s = (unsigned)__cvta_generic_to_shared(Qs);
    const unsigned ks_s = (unsigned)__cvta_generic_to_shared(Ks);
    const unsigned vs_s = (unsigned)__cvta_generic_to_shared(Vs);

    auto load_kv = [&](int kt, int st) {
        #pragma unroll
        for (int i = 0; i < 2; i++) {
            int ch = tid + i * 256;        // 0..511
            int r = ch >> 3, c = ch & 7;
            size_t gb = base + (size_t)(kt + r) * C3 + qoff;
            cp16s(ks_s + (st * KSTAGE + r * 72 + c * 8) * 2, qkv + gb + CDIM + c * 8);
            cp16s(vs_s + (st * KSTAGE + r * 72 + c * 8) * 2, qkv + gb + 2 * CDIM + c * 8);
        }
        if (tid < 64) msk[st][tid] = mask[bb * SEQ + kt + tid];
        asm volatile("cp.async.commit_group;\n");
    };

    // preload: Q + KV stage0 as group 0; KV stage1 as group 1
    #pragma unroll
    for (int i = 0; i < 4; i++) {
        int ch = tid + i * 256;
        int r = ch >> 3, c = ch & 7;
        cp16s(qs_s + (r * 72 + c * 8) * 2,
              qkv + base + (size_t)(q0 + r) * C3 + qoff + c * 8);
    }
    {
        #pragma unroll
        for (int i = 0; i < 2; i++) {
            int ch = tid + i * 256;
            int r = ch >> 3, c = ch & 7;
            size_t gb = base + (size_t)r * C3 + qoff;
            cp16s(ks_s + (r * 72 + c * 8) * 2, qkv + gb + CDIM + c * 8);
            cp16s(vs_s + (r * 72 + c * 8) * 2, qkv + gb + 2 * CDIM + c * 8);
        }
        if (tid < 64) msk[0][tid] = mask[bb * SEQ + tid];
        asm volatile("cp.async.commit_group;\n");
    }
    load_kv(64, 1);

    float m0 = -FLT_MAX, m1 = -FLT_MAX, l0 = 0.f, l1 = 0.f;
    float o[8][4] = {};

    int buf = 0, slot = 2;
    for (int it = 0; it < NKT; it++) {
        if (it + 1 < NKT) asm volatile("cp.async.wait_group 1;\n");
        else              asm volatile("cp.async.wait_group 0;\n");
        __syncthreads();

        if (it + 2 < NKT) {
            load_kv((it + 2) * 64, slot);
            slot = (slot + 1 == 3) ? 0 : slot + 1;
        }

        const unsigned kb_st = ks_b + buf * KSTAGE * 2;
        const unsigned vb_st = vs_b + buf * KSTAGE * 2;

        // ---- S = Q @ K^T ----
        float s[8][4] = {};
        #pragma unroll
        for (int ks = 0; ks < 64; ks += 16) {
            unsigned a[4], b[8][2];
            LDSM4(a[0], a[1], a[2], a[3], qs_b + ks * 2);
            #pragma unroll
            for (int g = 0; g < 4; g++)
                LDSM4(b[2 * g][0], b[2 * g][1], b[2 * g + 1][0], b[2 * g + 1][1],
                      kb_st + (g * 16 * 72) * 2 + ks * 2);
            #pragma unroll
            for (int ni = 0; ni < 8; ni++)
                MMA_F16(s[ni], a, b[ni]);
        }

        // ---- scale + mask + online softmax ----
        float mx0 = m0, mx1 = m1;
        #pragma unroll
        for (int ni = 0; ni < 8; ni++) {
            int t = ni * 8 + kq * 2;
            s[ni][0] *= 0.125f; s[ni][1] *= 0.125f;
            s[ni][2] *= 0.125f; s[ni][3] *= 0.125f;
            if (msk[buf][t] == 0)     { s[ni][0] = -FLT_MAX; s[ni][2] = -FLT_MAX; }
            if (msk[buf][t + 1] == 0) { s[ni][1] = -FLT_MAX; s[ni][3] = -FLT_MAX; }
            mx0 = fmaxf(mx0, fmaxf(s[ni][0], s[ni][1]));
            mx1 = fmaxf(mx1, fmaxf(s[ni][2], s[ni][3]));
        }
        mx0 = fmaxf(mx0, __shfl_xor_sync(0xffffffffu, mx0, 1));
        mx0 = fmaxf(mx0, __shfl_xor_sync(0xffffffffu, mx0, 2));
        mx1 = fmaxf(mx1, __shfl_xor_sync(0xffffffffu, mx1, 1));
        mx1 = fmaxf(mx1, __shfl_xor_sync(0xffffffffu, mx1, 2));

        float corr0 = __expf(m0 - mx0);
        float corr1 = __expf(m1 - mx1);
        m0 = mx0; m1 = mx1;

        float ls0 = 0.f, ls1 = 0.f;
        #pragma unroll
        for (int ni = 0; ni < 8; ni++) {
            float p00 = __expf(s[ni][0] - m0);
            float p01 = __expf(s[ni][1] - m0);
            float p10 = __expf(s[ni][2] - m1);
            float p11 = __expf(s[ni][3] - m1);
            ls0 += p00 + p01;
            ls1 += p10 + p11;
            int c = ni * 8 + kq * 2;
            *(__half2*)(Ps + (qrow + gr) * 72 + c)     = __floats2half2_rn(p00, p01);
            *(__half2*)(Ps + (qrow + gr + 8) * 72 + c) = __floats2half2_rn(p10, p11);
        }
        ls0 += __shfl_xor_sync(0xffffffffu, ls0, 1);
        ls0 += __shfl_xor_sync(0xffffffffu, ls0, 2);
        ls1 += __shfl_xor_sync(0xffffffffu, ls1, 1);
        ls1 += __shfl_xor_sync(0xffffffffu, ls1, 2);
        l0 = l0 * corr0 + ls0;
        l1 = l1 * corr1 + ls1;
        __syncwarp();                      // Ps rows are warp-private

        // ---- O = O*corr + P @ V ----
        #pragma unroll
        for (int di = 0; di < 8; di++) {
            o[di][0] *= corr0; o[di][1] *= corr0;
            o[di][2] *= corr1; o[di][3] *= corr1;
        }
        #pragma unroll
        for (int ks = 0; ks < 64; ks += 16) {
            unsigned a[4], b[8][2];
            LDSM4(a[0], a[1], a[2], a[3], ps_b + ks * 2);
            #pragma unroll
            for (int g = 0; g < 4; g++)
                LDSM4T(b[2 * g][0], b[2 * g][1], b[2 * g + 1][0], b[2 * g + 1][1],
                       vb_st + (ks * 72 + g * 16) * 2);
            #pragma unroll
            for (int di = 0; di < 8; di++)
                MMA_F16(o[di], a, b[di]);
        }
        buf = (buf + 1 == 3) ? 0 : buf + 1;
    }

    // ---- finalize + write fp16 ----
    float il0 = 1.0f / l0, il1 = 1.0f / l1;
    const int row0 = bb * SEQ + q0 + qrow + gr;
    #pragma unroll
    for (int di = 0; di < 8; di++) {
        int col = qoff + di * 8 + kq * 2;
        *(__half2*)(out + (size_t)row0 * CDIM + col) =
            __floats2half2_rn(o[di][0] * il0, o[di][1] * il0);
        *(__half2*)(out + (size_t)(row0 + 8) * CDIM + col) =
            __floats2half2_rn(o[di][2] * il1, o[di][3] * il1);
    }
}

// ---------------------------------------------------------------------------
// Launch
// ---------------------------------------------------------------------------
extern "C" void kernel_launch(void* const* d_in, const int* in_sizes, int n_in,
                              void* d_out, int out_size) {
    const float* x      = (const float*)d_in[0];
    const int*   mask   = (const int*)  d_in[1];
    const float* ln1_g  = (const float*)d_in[2];
    const float* ln1_b  = (const float*)d_in[3];
    const float* qkv_w  = (const float*)d_in[4];
    const float* qkv_b  = (const float*)d_in[5];
    const float* proj_w = (const float*)d_in[6];
    const float* proj_b = (const float*)d_in[7];
    const float* ln2_g  = (const float*)d_in[8];
    const float* ln2_b  = (const float*)d_in[9];
    const float* fc1_w  = (const float*)d_in[10];
    const float* fc1_b  = (const float*)d_in[11];
    const float* fc2_w  = (const float*)d_in[12];
    const float* fc2_b  = (const float*)d_in[13];
    float* out = (float*)d_out;

    __half *p_ln, *p_qkv, *p_attn, *p_act, *p_wqkv, *p_wproj, *p_wfc1, *p_wfc2;
    float  *p_x1;
    cudaGetSymbolAddress((void**)&p_ln,    g_ln);
    cudaGetSymbolAddress((void**)&p_qkv,   g_qkv);
    cudaGetSymbolAddress((void**)&p_attn,  g_attn);
    cudaGetSymbolAddress((void**)&p_x1,    g_x1);
    cudaGetSymbolAddress((void**)&p_act,   g_act);
    cudaGetSymbolAddress((void**)&p_wqkv,  g_wqkv);
    cudaGetSymbolAddress((void**)&p_wproj, g_wproj);
    cudaGetSymbolAddress((void**)&p_wfc1,  g_wfc1);
    cudaGetSymbolAddress((void**)&p_wfc2,  g_wfc2);

    cudaFuncSetAttribute(attn_f16, cudaFuncAttributeMaxDynamicSharedMemorySize,
                         ATTH_SMEM);
    cudaFuncSetAttribute(gemm_f16<false, false, true>,
                         cudaFuncAttributeMaxDynamicSharedMemorySize, GEMM_SMEM);
    cudaFuncSetAttribute(gemm_f16<false, true, false>,
                         cudaFuncAttributeMaxDynamicSharedMemorySize, GEMM_SMEM);
    cudaFuncSetAttribute(gemm_f16<true, false, true>,
                         cudaFuncAttributeMaxDynamicSharedMemorySize, GEMM_SMEM);

    // 0) transpose + fp16-convert weights to [N][K]
    transpose_h_kernel<<<dim3(C3 / 32, CDIM / 32), 256>>>(qkv_w, p_wqkv, CDIM, C3);
    transpose_h_kernel<<<dim3(CDIM / 32, CDIM / 32), 256>>>(proj_w, p_wproj, CDIM, CDIM);
    transpose_h_kernel<<<dim3(HID / 32, CDIM / 32), 256>>>(fc1_w, p_wfc1, CDIM, HID);
    transpose_h_kernel<<<dim3(CDIM / 32, HID / 32), 256>>>(fc2_w, p_wfc2, HID, CDIM);

    // 1) LN1 (fp16 out)
    layernorm_kernel<<<MROWS / 8, 256>>>(x, ln1_g, ln1_b, p_ln);

    // 2) QKV GEMM (fp16 out)
    gemm_f16<false, false, true><<<dim3(C3 / 128, MROWS / 128), 256, GEMM_SMEM>>>(
        MROWS, C3, CDIM, p_ln, p_wqkv, qkv_b, nullptr, p_qkv);

    // 3) fused attention (fp16 in/out)
    attn_f16<<<dim3(SEQ / 128, 4 * NHEAD), 256, ATTH_SMEM>>>(p_qkv, mask, p_attn);

    // 4) proj GEMM + residual (fp32 out)
    gemm_f16<false, true, false><<<dim3(CDIM / 128, MROWS / 128), 256, GEMM_SMEM>>>(
        MROWS, CDIM, CDIM, p_attn, p_wproj, proj_b, x, p_x1);

    // 5) LN2 (fp16 out)
    layernorm_kernel<<<MROWS / 8, 256>>>(p_x1, ln2_g, ln2_b, p_ln);

    // 6) FC1 + exact GELU (fp16 out)
    gemm_f16<true, false, true><<<dim3(HID / 128, MROWS / 128), 256, GEMM_SMEM>>>(
        MROWS, HID, CDIM, p_ln, p_wfc1, fc1_b, nullptr, p_act);

    // 7) FC2 + residual -> out (fp32)
    gemm_f16<false, true, false><<<dim3(CDIM / 128, MROWS / 128), 256, GEMM_SMEM>>>(
        MROWS, CDIM, HID, p_act, p_wfc2, fc2_b, p_x1, out);
}